// round 10
// baseline (speedup 1.0000x reference)
#include <cuda_runtime.h>
#include <cstdint>
#include <cstddef>

// Problem constants
#define NB 16
#define NC 128
#define HW 4096          // 64*64
#define MP 1024          // pooled positions (32*32)
#define K8 16            // C/8
#define K2 64            // C/2

// ---------------- scratch (device globals; no allocation allowed) ----------------
__device__ __align__(16) float g_f[NB * K8 * MP];                 // 1 MB
__device__ __align__(16) float g_g[NB * K8 * HW];                 // 4 MB
__device__ __align__(16) float g_v[NB * K2 * MP];                 // 4 MB
__device__ __align__(16) float g_beta[(size_t)NB * MP * HW];      // 256 MB

// ---------------- helpers ----------------
__device__ __forceinline__ float wredmax(float v) {
#pragma unroll
    for (int o = 16; o > 0; o >>= 1) v = fmaxf(v, __shfl_xor_sync(0xffffffffu, v, o));
    return v;
}
__device__ __forceinline__ float wredsum(float v) {
#pragma unroll
    for (int o = 16; o > 0; o >>= 1) v += __shfl_xor_sync(0xffffffffu, v, o);
    return v;
}

// =====================================================================
// Kernel 1: fused 1x1 convs (f,g,h) + 2x2 maxpool for f,h.
// Grid: (32 row-pairs, 16 batches), 384 threads.
// Dynamic smem: xs[128][128] (64KB) + ws[96][128] (48KB, reused as cs[80][128])
// =====================================================================
__global__ void __launch_bounds__(384) conv_pool_kernel(
    const float* __restrict__ x,
    const float* __restrict__ Wf, const float* __restrict__ bf,
    const float* __restrict__ Wg, const float* __restrict__ bg,
    const float* __restrict__ Wh, const float* __restrict__ bh)
{
    extern __shared__ float sm1[];
    float* xs = sm1;            // [128][128]  pix-contiguous
    float* ws = sm1 + 16384;    // [96][128]   k rows: 0..15 f, 16..31 g, 32..95 h
    __shared__ float bs[96];

    const int tid = threadIdx.x;
    const int hp  = blockIdx.x;   // pooled row 0..31
    const int b   = blockIdx.y;

    // weights -> smem
    {
        const float4* wf4 = (const float4*)Wf;
        const float4* wg4 = (const float4*)Wg;
        const float4* wh4 = (const float4*)Wh;
        float4* ws4 = (float4*)ws;
        for (int i = tid; i < 512;  i += 384) ws4[i]        = wf4[i];
        for (int i = tid; i < 512;  i += 384) ws4[512 + i]  = wg4[i];
        for (int i = tid; i < 2048; i += 384) ws4[1024 + i] = wh4[i];
        if (tid < 96) bs[tid] = (tid < 16) ? bf[tid] : ((tid < 32) ? bg[tid - 16] : bh[tid - 32]);
    }
    // x slab: rows 2hp, 2hp+1 for all 128 channels; 128 contiguous floats per channel
    {
        float4* xs4 = (float4*)xs;
        for (int i = tid; i < 4096; i += 384) {
            int c = i >> 5, p4 = i & 31;
            xs4[i] = *((const float4*)(x + (size_t)(b * NC + c) * HW + hp * 128) + p4);
        }
    }
    __syncthreads();

    // each thread: 4 consecutive output channels (kq) x 8 pixels (pg)
    const int kq = tid >> 4;        // 0..23
    const int pg = tid & 15;        // 0..15
    const int k0 = kq * 4;
    const int px = pg * 8;

    float acc[4][8];
#pragma unroll
    for (int i = 0; i < 4; i++)
#pragma unroll
        for (int j = 0; j < 8; j++) acc[i][j] = 0.f;

    const float* wr0 = ws + (k0 + 0) * 128;
    const float* wr1 = ws + (k0 + 1) * 128;
    const float* wr2 = ws + (k0 + 2) * 128;
    const float* wr3 = ws + (k0 + 3) * 128;

#pragma unroll 2
    for (int c = 0; c < 128; c += 4) {
        float4 w0 = *(const float4*)(wr0 + c);
        float4 w1 = *(const float4*)(wr1 + c);
        float4 w2 = *(const float4*)(wr2 + c);
        float4 w3 = *(const float4*)(wr3 + c);
        float wa0[4] = {w0.x, w0.y, w0.z, w0.w};
        float wa1[4] = {w1.x, w1.y, w1.z, w1.w};
        float wa2[4] = {w2.x, w2.y, w2.z, w2.w};
        float wa3[4] = {w3.x, w3.y, w3.z, w3.w};
#pragma unroll
        for (int ci = 0; ci < 4; ci++) {
            float4 xa = *(const float4*)(xs + (c + ci) * 128 + px);
            float4 xb = *(const float4*)(xs + (c + ci) * 128 + px + 4);
            float xv[8] = {xa.x, xa.y, xa.z, xa.w, xb.x, xb.y, xb.z, xb.w};
#pragma unroll
            for (int j = 0; j < 8; j++) {
                acc[0][j] = fmaf(wa0[ci], xv[j], acc[0][j]);
                acc[1][j] = fmaf(wa1[ci], xv[j], acc[1][j]);
                acc[2][j] = fmaf(wa2[ci], xv[j], acc[2][j]);
                acc[3][j] = fmaf(wa3[ci], xv[j], acc[3][j]);
            }
        }
    }
    __syncthreads();   // done with xs & ws reads; ws region reused as cs below

    const int r    = pg >> 3;         // row within pair
    const int colb = (pg & 7) * 8;    // column base (0..56)

    if (kq >= 4 && kq < 8) {
        // g channels: full resolution, write directly
#pragma unroll
        for (int i = 0; i < 4; i++) {
            const int k = k0 + i;                 // 16..31
            const float bias = bs[k];
            float* gp = g_g + (size_t)(b * K8 + (k - 16)) * HW + (2 * hp + r) * 64 + colb;
            *(float4*)gp       = make_float4(acc[i][0] + bias, acc[i][1] + bias,
                                             acc[i][2] + bias, acc[i][3] + bias);
            *(float4*)(gp + 4) = make_float4(acc[i][4] + bias, acc[i][5] + bias,
                                             acc[i][6] + bias, acc[i][7] + bias);
        }
    } else {
        // f (k<16) and h (k>=32) channels: stage in smem for pooling
        float* cs = ws;   // [80][128]: 0..15 f, 16..79 h
#pragma unroll
        for (int i = 0; i < 4; i++) {
            const int k = k0 + i;
            const int kfh = (k < 16) ? k : (k - 16);
            const float bias = bs[k];
            float* dst = cs + kfh * 128 + px;
            *(float4*)dst       = make_float4(acc[i][0] + bias, acc[i][1] + bias,
                                              acc[i][2] + bias, acc[i][3] + bias);
            *(float4*)(dst + 4) = make_float4(acc[i][4] + bias, acc[i][5] + bias,
                                              acc[i][6] + bias, acc[i][7] + bias);
        }
    }
    __syncthreads();

    // 2x2 maxpool and writeout: 80 channels x 32 pooled cols
    for (int idx = tid; idx < 2560; idx += 384) {
        int k = idx >> 5, wc = idx & 31;
        const float* csr = ws + k * 128;
        float mv = fmaxf(fmaxf(csr[2 * wc], csr[2 * wc + 1]),
                         fmaxf(csr[64 + 2 * wc], csr[64 + 2 * wc + 1]));
        int m = hp * 32 + wc;
        if (k < 16) g_f[(size_t)(b * K8 + k) * MP + m]        = mv;
        else        g_v[(size_t)(b * K2 + (k - 16)) * MP + m] = mv;
    }
}

// =====================================================================
// Kernel 2: s = f^T g (K=16) fused with row softmax -> beta.  s never hits HBM.
// Grid: (256 m-groups of 4, 16 batches), 512 threads. Each thread: 4 rows x 8 cols.
// =====================================================================
__global__ void __launch_bounds__(512) s_softmax_kernel()
{
    const int b   = blockIdx.y;
    const int m0  = blockIdx.x * 4;
    const int tid = threadIdx.x;

    __shared__ float fs[16][4];
    __shared__ float red[4][16];

    if (tid < 64)
        fs[tid >> 2][tid & 3] = g_f[(size_t)(b * K8 + (tid >> 2)) * MP + m0 + (tid & 3)];
    __syncthreads();

    const float* gb = g_g + (size_t)b * K8 * HW;
    const int n0 = tid * 4;   // cols [n0,n0+3] and [2048+n0, 2048+n0+3]

    float acc[4][8];
#pragma unroll
    for (int mi = 0; mi < 4; mi++)
#pragma unroll
        for (int j = 0; j < 8; j++) acc[mi][j] = 0.f;

#pragma unroll
    for (int k = 0; k < 16; k++) {
        const float* gk = gb + (size_t)k * HW;
        float4 ga = *(const float4*)(gk + n0);
        float4 gc = *(const float4*)(gk + 2048 + n0);
        float gv[8] = {ga.x, ga.y, ga.z, ga.w, gc.x, gc.y, gc.z, gc.w};
#pragma unroll
        for (int mi = 0; mi < 4; mi++) {
            const float fv = fs[k][mi];
#pragma unroll
            for (int j = 0; j < 8; j++) acc[mi][j] = fmaf(fv, gv[j], acc[mi][j]);
        }
    }

    const int lane = tid & 31, wid = tid >> 5;

    // --- row max ---
    float rmx[4];
#pragma unroll
    for (int mi = 0; mi < 4; mi++) {
        float v = acc[mi][0];
#pragma unroll
        for (int j = 1; j < 8; j++) v = fmaxf(v, acc[mi][j]);
        rmx[mi] = wredmax(v);
    }
    if (lane == 0) {
#pragma unroll
        for (int mi = 0; mi < 4; mi++) red[mi][wid] = rmx[mi];
    }
    __syncthreads();
    float mxf[4];
#pragma unroll
    for (int mi = 0; mi < 4; mi++) {
        float v = red[mi][0];
#pragma unroll
        for (int w2 = 1; w2 < 16; w2++) v = fmaxf(v, red[mi][w2]);
        mxf[mi] = v;
    }
    __syncthreads();   // before reusing red[]

    // --- exp + row sum ---
    float sms[4];
#pragma unroll
    for (int mi = 0; mi < 4; mi++) {
        float s = 0.f;
#pragma unroll
        for (int j = 0; j < 8; j++) {
            acc[mi][j] = __expf(acc[mi][j] - mxf[mi]);
            s += acc[mi][j];
        }
        sms[mi] = wredsum(s);
    }
    if (lane == 0) {
#pragma unroll
        for (int mi = 0; mi < 4; mi++) red[mi][wid] = sms[mi];
    }
    __syncthreads();

#pragma unroll
    for (int mi = 0; mi < 4; mi++) {
        float s = 0.f;
#pragma unroll
        for (int w2 = 0; w2 < 16; w2++) s += red[mi][w2];
        const float inv = 1.0f / s;
        float* bp = g_beta + (size_t)(b * MP + m0 + mi) * HW + n0;
        *(float4*)bp          = make_float4(acc[mi][0] * inv, acc[mi][1] * inv,
                                            acc[mi][2] * inv, acc[mi][3] * inv);
        *(float4*)(bp + 2048) = make_float4(acc[mi][4] * inv, acc[mi][5] * inv,
                                            acc[mi][6] * inv, acc[mi][7] * inv);
    }
}

// =====================================================================
// Kernel 3: o = v @ beta  (64x4096 per batch, K=1024), fused with
// out = gamma*(Wo @ o + bo) + x.
// Grid: (32 column blocks of 128, 16 batches), 256 threads (tx 0..15, ty 0..15).
// Dyn smem: main loop As[32][68] + Bs[32][128]; epilogue Os[64][132] + WoT[64][128].
// =====================================================================
__global__ void __launch_bounds__(256) attn_out_kernel(
    const float* __restrict__ x, const float* __restrict__ Wo,
    const float* __restrict__ bo, const float* __restrict__ gammap,
    float* __restrict__ out)
{
    extern __shared__ float sm3[];
    float* As = sm3;           // [32][68]   (mi, k) with pad
    float* Bs = sm3 + 2176;    // [32][128]  (mi, n)

    const int b   = blockIdx.y;
    const int nb  = blockIdx.x * 128;
    const int tid = threadIdx.x;
    const int tx  = tid & 15, ty = tid >> 4;
    const int miL = tid & 31, kg = tid >> 5;

    const float* vB    = g_v    + (size_t)b * K2 * MP;
    const float* betaB = g_beta + (size_t)b * MP * HW + nb;

    float acc[4][8];
#pragma unroll
    for (int i = 0; i < 4; i++)
#pragma unroll
        for (int j = 0; j < 8; j++) acc[i][j] = 0.f;

    float  rA[8];
    float4 rB[4];

    // prefetch chunk 0
#pragma unroll
    for (int ii = 0; ii < 8; ii++) rA[ii] = vB[(size_t)(kg + ii * 8) * MP + miL];
#pragma unroll
    for (int it = 0; it < 4; it++) {
        int lin = it * 1024 + tid * 4;
        rB[it] = *(const float4*)(betaB + (size_t)(lin >> 7) * HW + (lin & 127));
    }
#pragma unroll
    for (int ii = 0; ii < 8; ii++) As[miL * 68 + kg + ii * 8] = rA[ii];
#pragma unroll
    for (int it = 0; it < 4; it++) *(float4*)(Bs + it * 1024 + tid * 4) = rB[it];
    __syncthreads();

    for (int c = 0; c < 32; c++) {
        const int mcn = (c + 1) * 32;
        if (c < 31) {
#pragma unroll
            for (int ii = 0; ii < 8; ii++)
                rA[ii] = vB[(size_t)(kg + ii * 8) * MP + mcn + miL];
#pragma unroll
            for (int it = 0; it < 4; it++) {
                int lin = it * 1024 + tid * 4;
                rB[it] = *(const float4*)(betaB + (size_t)(mcn + (lin >> 7)) * HW + (lin & 127));
            }
        }
#pragma unroll
        for (int mi = 0; mi < 32; mi++) {
            float4 a  = *(const float4*)(As + mi * 68 + ty * 4);
            float4 b0 = *(const float4*)(Bs + mi * 128 + tx * 8);
            float4 b1 = *(const float4*)(Bs + mi * 128 + tx * 8 + 4);
            float av[4] = {a.x, a.y, a.z, a.w};
            float bv[8] = {b0.x, b0.y, b0.z, b0.w, b1.x, b1.y, b1.z, b1.w};
#pragma unroll
            for (int i = 0; i < 4; i++)
#pragma unroll
                for (int j = 0; j < 8; j++)
                    acc[i][j] = fmaf(av[i], bv[j], acc[i][j]);
        }
        __syncthreads();
        if (c < 31) {
#pragma unroll
            for (int ii = 0; ii < 8; ii++) As[miL * 68 + kg + ii * 8] = rA[ii];
#pragma unroll
            for (int it = 0; it < 4; it++) *(float4*)(Bs + it * 1024 + tid * 4) = rB[it];
            __syncthreads();
        }
    }

    // ---------------- epilogue: out = gamma*(Wo @ o + bo) + x ----------------
    float* Os  = sm3;          // [64][132]
    float* WoT = sm3 + 8448;   // [64][128]  WoT[k][c] = Wo[c][k]

#pragma unroll
    for (int i2 = 0; i2 < 4; i2++) {
        int k = ty * 4 + i2;
        *(float4*)(Os + k * 132 + tx * 8)     = make_float4(acc[i2][0], acc[i2][1],
                                                            acc[i2][2], acc[i2][3]);
        *(float4*)(Os + k * 132 + tx * 8 + 4) = make_float4(acc[i2][4], acc[i2][5],
                                                            acc[i2][6], acc[i2][7]);
    }
    for (int i = tid; i < 8192; i += 256) {
        int k = i >> 7, cc = i & 127;
        WoT[i] = Wo[cc * 64 + k];
    }
    __syncthreads();

    const float gma = *gammap;
    float acc2[8][8];
#pragma unroll
    for (int i = 0; i < 8; i++)
#pragma unroll
        for (int j = 0; j < 8; j++) acc2[i][j] = 0.f;

#pragma unroll 4
    for (int k = 0; k < 64; k++) {
        float4 w0 = *(const float4*)(WoT + k * 128 + ty * 8);
        float4 w1 = *(const float4*)(WoT + k * 128 + ty * 8 + 4);
        float4 o0 = *(const float4*)(Os + k * 132 + tx * 8);
        float4 o1 = *(const float4*)(Os + k * 132 + tx * 8 + 4);
        float wv[8] = {w0.x, w0.y, w0.z, w0.w, w1.x, w1.y, w1.z, w1.w};
        float ov[8] = {o0.x, o0.y, o0.z, o0.w, o1.x, o1.y, o1.z, o1.w};
#pragma unroll
        for (int i = 0; i < 8; i++)
#pragma unroll
            for (int j = 0; j < 8; j++)
                acc2[i][j] = fmaf(wv[i], ov[j], acc2[i][j]);
    }

#pragma unroll
    for (int rr = 0; rr < 8; rr++) {
        const int cc = ty * 8 + rr;
        const float bias = bo[cc];
        const size_t off = (size_t)(b * NC + cc) * HW + nb + tx * 8;
        float4 x0 = *(const float4*)(x + off);
        float4 x1 = *(const float4*)(x + off + 4);
        float4 r0, r1;
        r0.x = fmaf(gma, acc2[rr][0] + bias, x0.x);
        r0.y = fmaf(gma, acc2[rr][1] + bias, x0.y);
        r0.z = fmaf(gma, acc2[rr][2] + bias, x0.z);
        r0.w = fmaf(gma, acc2[rr][3] + bias, x0.w);
        r1.x = fmaf(gma, acc2[rr][4] + bias, x1.x);
        r1.y = fmaf(gma, acc2[rr][5] + bias, x1.y);
        r1.z = fmaf(gma, acc2[rr][6] + bias, x1.z);
        r1.w = fmaf(gma, acc2[rr][7] + bias, x1.w);
        *(float4*)(out + off)     = r0;
        *(float4*)(out + off + 4) = r1;
    }
}

// =====================================================================
extern "C" void kernel_launch(void* const* d_in, const int* in_sizes, int n_in,
                              void* d_out, int out_size)
{
    (void)in_sizes; (void)n_in; (void)out_size;
    const float* x     = (const float*)d_in[0];
    const float* Wf    = (const float*)d_in[1];
    const float* bf    = (const float*)d_in[2];
    const float* Wg    = (const float*)d_in[3];
    const float* bg    = (const float*)d_in[4];
    const float* Wh    = (const float*)d_in[5];
    const float* bh    = (const float*)d_in[6];
    const float* Wo    = (const float*)d_in[7];
    const float* bo    = (const float*)d_in[8];
    const float* gamma = (const float*)d_in[9];
    float* out = (float*)d_out;

    // opt-in large dynamic smem (idempotent; safe under graph capture)
    cudaFuncSetAttribute(conv_pool_kernel,
                         cudaFuncAttributeMaxDynamicSharedMemorySize, 114688);
    cudaFuncSetAttribute(attn_out_kernel,
                         cudaFuncAttributeMaxDynamicSharedMemorySize, 66560);

    conv_pool_kernel<<<dim3(32, NB), 384, 114688>>>(x, Wf, bf, Wg, bg, Wh, bh);
    s_softmax_kernel<<<dim3(256, NB), 512>>>();
    attn_out_kernel<<<dim3(32, NB), 256, 66560>>>(x, Wo, bo, gamma, out);
}

// round 11
// speedup vs baseline: 1.0001x; 1.0001x over previous
#include <cuda_runtime.h>
#include <cstdint>
#include <cstddef>

// Problem constants
#define NB 16
#define NC 128
#define HW 4096          // 64*64
#define MP 1024          // pooled positions (32*32)
#define K8 16            // C/8
#define K2 64            // C/2

// ---------------- scratch (device globals; no allocation allowed) ----------------
__device__ __align__(16) float g_f[NB * K8 * MP];                 // 1 MB
__device__ __align__(16) float g_g[NB * K8 * HW];                 // 4 MB
__device__ __align__(16) float g_v[NB * K2 * MP];                 // 4 MB
__device__ __align__(16) float g_beta[(size_t)NB * MP * HW];      // 256 MB

// ---------------- helpers ----------------
__device__ __forceinline__ float wredmax(float v) {
#pragma unroll
    for (int o = 16; o > 0; o >>= 1) v = fmaxf(v, __shfl_xor_sync(0xffffffffu, v, o));
    return v;
}
__device__ __forceinline__ float wredsum(float v) {
#pragma unroll
    for (int o = 16; o > 0; o >>= 1) v += __shfl_xor_sync(0xffffffffu, v, o);
    return v;
}

// =====================================================================
// Kernel 1: fused 1x1 convs (f,g,h) + 2x2 maxpool for f,h.
// Grid: (32 row-pairs, 16 batches), 384 threads.
// Dynamic smem: xs[128][128] (64KB) + ws[96][128] (48KB, reused as cs[80][128])
// =====================================================================
__global__ void __launch_bounds__(384) conv_pool_kernel(
    const float* __restrict__ x,
    const float* __restrict__ Wf, const float* __restrict__ bf,
    const float* __restrict__ Wg, const float* __restrict__ bg,
    const float* __restrict__ Wh, const float* __restrict__ bh)
{
    extern __shared__ float sm1[];
    float* xs = sm1;            // [128][128]  pix-contiguous
    float* ws = sm1 + 16384;    // [96][128]   k rows: 0..15 f, 16..31 g, 32..95 h
    __shared__ float bs[96];

    const int tid = threadIdx.x;
    const int hp  = blockIdx.x;   // pooled row 0..31
    const int b   = blockIdx.y;

    // weights -> smem
    {
        const float4* wf4 = (const float4*)Wf;
        const float4* wg4 = (const float4*)Wg;
        const float4* wh4 = (const float4*)Wh;
        float4* ws4 = (float4*)ws;
        for (int i = tid; i < 512;  i += 384) ws4[i]        = wf4[i];
        for (int i = tid; i < 512;  i += 384) ws4[512 + i]  = wg4[i];
        for (int i = tid; i < 2048; i += 384) ws4[1024 + i] = wh4[i];
        if (tid < 96) bs[tid] = (tid < 16) ? bf[tid] : ((tid < 32) ? bg[tid - 16] : bh[tid - 32]);
    }
    // x slab: rows 2hp, 2hp+1 for all 128 channels; 128 contiguous floats per channel
    {
        float4* xs4 = (float4*)xs;
        for (int i = tid; i < 4096; i += 384) {
            int c = i >> 5, p4 = i & 31;
            xs4[i] = *((const float4*)(x + (size_t)(b * NC + c) * HW + hp * 128) + p4);
        }
    }
    __syncthreads();

    // each thread: 4 consecutive output channels (kq) x 8 pixels (pg)
    const int kq = tid >> 4;        // 0..23
    const int pg = tid & 15;        // 0..15
    const int k0 = kq * 4;
    const int px = pg * 8;

    float acc[4][8];
#pragma unroll
    for (int i = 0; i < 4; i++)
#pragma unroll
        for (int j = 0; j < 8; j++) acc[i][j] = 0.f;

    const float* wr0 = ws + (k0 + 0) * 128;
    const float* wr1 = ws + (k0 + 1) * 128;
    const float* wr2 = ws + (k0 + 2) * 128;
    const float* wr3 = ws + (k0 + 3) * 128;

#pragma unroll 2
    for (int c = 0; c < 128; c += 4) {
        float4 w0 = *(const float4*)(wr0 + c);
        float4 w1 = *(const float4*)(wr1 + c);
        float4 w2 = *(const float4*)(wr2 + c);
        float4 w3 = *(const float4*)(wr3 + c);
        float wa0[4] = {w0.x, w0.y, w0.z, w0.w};
        float wa1[4] = {w1.x, w1.y, w1.z, w1.w};
        float wa2[4] = {w2.x, w2.y, w2.z, w2.w};
        float wa3[4] = {w3.x, w3.y, w3.z, w3.w};
#pragma unroll
        for (int ci = 0; ci < 4; ci++) {
            float4 xa = *(const float4*)(xs + (c + ci) * 128 + px);
            float4 xb = *(const float4*)(xs + (c + ci) * 128 + px + 4);
            float xv[8] = {xa.x, xa.y, xa.z, xa.w, xb.x, xb.y, xb.z, xb.w};
#pragma unroll
            for (int j = 0; j < 8; j++) {
                acc[0][j] = fmaf(wa0[ci], xv[j], acc[0][j]);
                acc[1][j] = fmaf(wa1[ci], xv[j], acc[1][j]);
                acc[2][j] = fmaf(wa2[ci], xv[j], acc[2][j]);
                acc[3][j] = fmaf(wa3[ci], xv[j], acc[3][j]);
            }
        }
    }
    __syncthreads();   // done with xs & ws reads; ws region reused as cs below

    const int r    = pg >> 3;         // row within pair
    const int colb = (pg & 7) * 8;    // column base (0..56)

    if (kq >= 4 && kq < 8) {
        // g channels: full resolution, write directly
#pragma unroll
        for (int i = 0; i < 4; i++) {
            const int k = k0 + i;                 // 16..31
            const float bias = bs[k];
            float* gp = g_g + (size_t)(b * K8 + (k - 16)) * HW + (2 * hp + r) * 64 + colb;
            *(float4*)gp       = make_float4(acc[i][0] + bias, acc[i][1] + bias,
                                             acc[i][2] + bias, acc[i][3] + bias);
            *(float4*)(gp + 4) = make_float4(acc[i][4] + bias, acc[i][5] + bias,
                                             acc[i][6] + bias, acc[i][7] + bias);
        }
    } else {
        // f (k<16) and h (k>=32) channels: stage in smem for pooling
        float* cs = ws;   // [80][128]: 0..15 f, 16..79 h
#pragma unroll
        for (int i = 0; i < 4; i++) {
            const int k = k0 + i;
            const int kfh = (k < 16) ? k : (k - 16);
            const float bias = bs[k];
            float* dst = cs + kfh * 128 + px;
            *(float4*)dst       = make_float4(acc[i][0] + bias, acc[i][1] + bias,
                                              acc[i][2] + bias, acc[i][3] + bias);
            *(float4*)(dst + 4) = make_float4(acc[i][4] + bias, acc[i][5] + bias,
                                              acc[i][6] + bias, acc[i][7] + bias);
        }
    }
    __syncthreads();

    // 2x2 maxpool and writeout: 80 channels x 32 pooled cols
    for (int idx = tid; idx < 2560; idx += 384) {
        int k = idx >> 5, wc = idx & 31;
        const float* csr = ws + k * 128;
        float mv = fmaxf(fmaxf(csr[2 * wc], csr[2 * wc + 1]),
                         fmaxf(csr[64 + 2 * wc], csr[64 + 2 * wc + 1]));
        int m = hp * 32 + wc;
        if (k < 16) g_f[(size_t)(b * K8 + k) * MP + m]        = mv;
        else        g_v[(size_t)(b * K2 + (k - 16)) * MP + m] = mv;
    }
}

// =====================================================================
// Kernel 2: s = f^T g (K=16) fused with row softmax -> beta.  s never hits HBM.
// Grid: (256 m-groups of 4, 16 batches), 512 threads. Each thread: 4 rows x 8 cols.
// =====================================================================
__global__ void __launch_bounds__(512) s_softmax_kernel()
{
    const int b   = blockIdx.y;
    const int m0  = blockIdx.x * 4;
    const int tid = threadIdx.x;

    __shared__ float fs[16][4];
    __shared__ float red[4][16];

    if (tid < 64)
        fs[tid >> 2][tid & 3] = g_f[(size_t)(b * K8 + (tid >> 2)) * MP + m0 + (tid & 3)];
    __syncthreads();

    const float* gb = g_g + (size_t)b * K8 * HW;
    const int n0 = tid * 4;   // cols [n0,n0+3] and [2048+n0, 2048+n0+3]

    float acc[4][8];
#pragma unroll
    for (int mi = 0; mi < 4; mi++)
#pragma unroll
        for (int j = 0; j < 8; j++) acc[mi][j] = 0.f;

#pragma unroll
    for (int k = 0; k < 16; k++) {
        const float* gk = gb + (size_t)k * HW;
        float4 ga = *(const float4*)(gk + n0);
        float4 gc = *(const float4*)(gk + 2048 + n0);
        float gv[8] = {ga.x, ga.y, ga.z, ga.w, gc.x, gc.y, gc.z, gc.w};
#pragma unroll
        for (int mi = 0; mi < 4; mi++) {
            const float fv = fs[k][mi];
#pragma unroll
            for (int j = 0; j < 8; j++) acc[mi][j] = fmaf(fv, gv[j], acc[mi][j]);
        }
    }

    const int lane = tid & 31, wid = tid >> 5;

    // --- row max ---
    float rmx[4];
#pragma unroll
    for (int mi = 0; mi < 4; mi++) {
        float v = acc[mi][0];
#pragma unroll
        for (int j = 1; j < 8; j++) v = fmaxf(v, acc[mi][j]);
        rmx[mi] = wredmax(v);
    }
    if (lane == 0) {
#pragma unroll
        for (int mi = 0; mi < 4; mi++) red[mi][wid] = rmx[mi];
    }
    __syncthreads();
    float mxf[4];
#pragma unroll
    for (int mi = 0; mi < 4; mi++) {
        float v = red[mi][0];
#pragma unroll
        for (int w2 = 1; w2 < 16; w2++) v = fmaxf(v, red[mi][w2]);
        mxf[mi] = v;
    }
    __syncthreads();   // before reusing red[]

    // --- exp + row sum ---
    float sms[4];
#pragma unroll
    for (int mi = 0; mi < 4; mi++) {
        float s = 0.f;
#pragma unroll
        for (int j = 0; j < 8; j++) {
            acc[mi][j] = __expf(acc[mi][j] - mxf[mi]);
            s += acc[mi][j];
        }
        sms[mi] = wredsum(s);
    }
    if (lane == 0) {
#pragma unroll
        for (int mi = 0; mi < 4; mi++) red[mi][wid] = sms[mi];
    }
    __syncthreads();

#pragma unroll
    for (int mi = 0; mi < 4; mi++) {
        float s = 0.f;
#pragma unroll
        for (int w2 = 0; w2 < 16; w2++) s += red[mi][w2];
        const float inv = 1.0f / s;
        float* bp = g_beta + (size_t)(b * MP + m0 + mi) * HW + n0;
        *(float4*)bp          = make_float4(acc[mi][0] * inv, acc[mi][1] * inv,
                                            acc[mi][2] * inv, acc[mi][3] * inv);
        *(float4*)(bp + 2048) = make_float4(acc[mi][4] * inv, acc[mi][5] * inv,
                                            acc[mi][6] * inv, acc[mi][7] * inv);
    }
}

// =====================================================================
// Kernel 3: o = v @ beta  (64x4096 per batch, K=1024), fused with
// out = gamma*(Wo @ o + bo) + x.
// Grid: (32 column blocks of 128, 16 batches), 256 threads (tx 0..15, ty 0..15).
// Dyn smem: main loop As[32][68] + Bs[32][128]; epilogue Os[64][132] + WoT[64][128].
// =====================================================================
__global__ void __launch_bounds__(256) attn_out_kernel(
    const float* __restrict__ x, const float* __restrict__ Wo,
    const float* __restrict__ bo, const float* __restrict__ gammap,
    float* __restrict__ out)
{
    extern __shared__ float sm3[];
    float* As = sm3;           // [32][68]   (mi, k) with pad
    float* Bs = sm3 + 2176;    // [32][128]  (mi, n)

    const int b   = blockIdx.y;
    const int nb  = blockIdx.x * 128;
    const int tid = threadIdx.x;
    const int tx  = tid & 15, ty = tid >> 4;
    const int miL = tid & 31, kg = tid >> 5;

    const float* vB    = g_v    + (size_t)b * K2 * MP;
    const float* betaB = g_beta + (size_t)b * MP * HW + nb;

    float acc[4][8];
#pragma unroll
    for (int i = 0; i < 4; i++)
#pragma unroll
        for (int j = 0; j < 8; j++) acc[i][j] = 0.f;

    float  rA[8];
    float4 rB[4];

    // prefetch chunk 0
#pragma unroll
    for (int ii = 0; ii < 8; ii++) rA[ii] = vB[(size_t)(kg + ii * 8) * MP + miL];
#pragma unroll
    for (int it = 0; it < 4; it++) {
        int lin = it * 1024 + tid * 4;
        rB[it] = *(const float4*)(betaB + (size_t)(lin >> 7) * HW + (lin & 127));
    }
#pragma unroll
    for (int ii = 0; ii < 8; ii++) As[miL * 68 + kg + ii * 8] = rA[ii];
#pragma unroll
    for (int it = 0; it < 4; it++) *(float4*)(Bs + it * 1024 + tid * 4) = rB[it];
    __syncthreads();

    for (int c = 0; c < 32; c++) {
        const int mcn = (c + 1) * 32;
        if (c < 31) {
#pragma unroll
            for (int ii = 0; ii < 8; ii++)
                rA[ii] = vB[(size_t)(kg + ii * 8) * MP + mcn + miL];
#pragma unroll
            for (int it = 0; it < 4; it++) {
                int lin = it * 1024 + tid * 4;
                rB[it] = *(const float4*)(betaB + (size_t)(mcn + (lin >> 7)) * HW + (lin & 127));
            }
        }
#pragma unroll
        for (int mi = 0; mi < 32; mi++) {
            float4 a  = *(const float4*)(As + mi * 68 + ty * 4);
            float4 b0 = *(const float4*)(Bs + mi * 128 + tx * 8);
            float4 b1 = *(const float4*)(Bs + mi * 128 + tx * 8 + 4);
            float av[4] = {a.x, a.y, a.z, a.w};
            float bv[8] = {b0.x, b0.y, b0.z, b0.w, b1.x, b1.y, b1.z, b1.w};
#pragma unroll
            for (int i = 0; i < 4; i++)
#pragma unroll
                for (int j = 0; j < 8; j++)
                    acc[i][j] = fmaf(av[i], bv[j], acc[i][j]);
        }
        __syncthreads();
        if (c < 31) {
#pragma unroll
            for (int ii = 0; ii < 8; ii++) As[miL * 68 + kg + ii * 8] = rA[ii];
#pragma unroll
            for (int it = 0; it < 4; it++) *(float4*)(Bs + it * 1024 + tid * 4) = rB[it];
            __syncthreads();
        }
    }

    // ---------------- epilogue: out = gamma*(Wo @ o + bo) + x ----------------
    float* Os  = sm3;          // [64][132]
    float* WoT = sm3 + 8448;   // [64][128]  WoT[k][c] = Wo[c][k]

#pragma unroll
    for (int i2 = 0; i2 < 4; i2++) {
        int k = ty * 4 + i2;
        *(float4*)(Os + k * 132 + tx * 8)     = make_float4(acc[i2][0], acc[i2][1],
                                                            acc[i2][2], acc[i2][3]);
        *(float4*)(Os + k * 132 + tx * 8 + 4) = make_float4(acc[i2][4], acc[i2][5],
                                                            acc[i2][6], acc[i2][7]);
    }
    for (int i = tid; i < 8192; i += 256) {
        int k = i >> 7, cc = i & 127;
        WoT[i] = Wo[cc * 64 + k];
    }
    __syncthreads();

    const float gma = *gammap;
    float acc2[8][8];
#pragma unroll
    for (int i = 0; i < 8; i++)
#pragma unroll
        for (int j = 0; j < 8; j++) acc2[i][j] = 0.f;

#pragma unroll 4
    for (int k = 0; k < 64; k++) {
        float4 w0 = *(const float4*)(WoT + k * 128 + ty * 8);
        float4 w1 = *(const float4*)(WoT + k * 128 + ty * 8 + 4);
        float4 o0 = *(const float4*)(Os + k * 132 + tx * 8);
        float4 o1 = *(const float4*)(Os + k * 132 + tx * 8 + 4);
        float wv[8] = {w0.x, w0.y, w0.z, w0.w, w1.x, w1.y, w1.z, w1.w};
        float ov[8] = {o0.x, o0.y, o0.z, o0.w, o1.x, o1.y, o1.z, o1.w};
#pragma unroll
        for (int i = 0; i < 8; i++)
#pragma unroll
            for (int j = 0; j < 8; j++)
                acc2[i][j] = fmaf(wv[i], ov[j], acc2[i][j]);
    }

#pragma unroll
    for (int rr = 0; rr < 8; rr++) {
        const int cc = ty * 8 + rr;
        const float bias = bo[cc];
        const size_t off = (size_t)(b * NC + cc) * HW + nb + tx * 8;
        float4 x0 = *(const float4*)(x + off);
        float4 x1 = *(const float4*)(x + off + 4);
        float4 r0, r1;
        r0.x = fmaf(gma, acc2[rr][0] + bias, x0.x);
        r0.y = fmaf(gma, acc2[rr][1] + bias, x0.y);
        r0.z = fmaf(gma, acc2[rr][2] + bias, x0.z);
        r0.w = fmaf(gma, acc2[rr][3] + bias, x0.w);
        r1.x = fmaf(gma, acc2[rr][4] + bias, x1.x);
        r1.y = fmaf(gma, acc2[rr][5] + bias, x1.y);
        r1.z = fmaf(gma, acc2[rr][6] + bias, x1.z);
        r1.w = fmaf(gma, acc2[rr][7] + bias, x1.w);
        *(float4*)(out + off)     = r0;
        *(float4*)(out + off + 4) = r1;
    }
}

// =====================================================================
extern "C" void kernel_launch(void* const* d_in, const int* in_sizes, int n_in,
                              void* d_out, int out_size)
{
    (void)in_sizes; (void)n_in; (void)out_size;
    const float* x     = (const float*)d_in[0];
    const float* Wf    = (const float*)d_in[1];
    const float* bf    = (const float*)d_in[2];
    const float* Wg    = (const float*)d_in[3];
    const float* bg    = (const float*)d_in[4];
    const float* Wh    = (const float*)d_in[5];
    const float* bh    = (const float*)d_in[6];
    const float* Wo    = (const float*)d_in[7];
    const float* bo    = (const float*)d_in[8];
    const float* gamma = (const float*)d_in[9];
    float* out = (float*)d_out;

    // opt-in large dynamic smem (idempotent; safe under graph capture)
    cudaFuncSetAttribute(conv_pool_kernel,
                         cudaFuncAttributeMaxDynamicSharedMemorySize, 114688);
    cudaFuncSetAttribute(attn_out_kernel,
                         cudaFuncAttributeMaxDynamicSharedMemorySize, 66560);

    conv_pool_kernel<<<dim3(32, NB), 384, 114688>>>(x, Wf, bf, Wg, bg, Wh, bh);
    s_softmax_kernel<<<dim3(256, NB), 512>>>();
    attn_out_kernel<<<dim3(32, NB), 256, 66560>>>(x, Wo, bo, gamma, out);
}

// round 12
// speedup vs baseline: 1.0008x; 1.0007x over previous
#include <cuda_runtime.h>
#include <cstdint>
#include <cstddef>

// Problem constants
#define NB 16
#define NC 128
#define HW 4096          // 64*64
#define MP 1024          // pooled positions (32*32)
#define K8 16            // C/8
#define K2 64            // C/2

// ---------------- scratch (device globals; no allocation allowed) ----------------
__device__ __align__(16) float g_f[NB * K8 * MP];                 // 1 MB
__device__ __align__(16) float g_g[NB * K8 * HW];                 // 4 MB
__device__ __align__(16) float g_v[NB * K2 * MP];                 // 4 MB
__device__ __align__(16) float g_beta[(size_t)NB * MP * HW];      // 256 MB

// ---------------- helpers ----------------
__device__ __forceinline__ float wredmax(float v) {
#pragma unroll
    for (int o = 16; o > 0; o >>= 1) v = fmaxf(v, __shfl_xor_sync(0xffffffffu, v, o));
    return v;
}
__device__ __forceinline__ float wredsum(float v) {
#pragma unroll
    for (int o = 16; o > 0; o >>= 1) v += __shfl_xor_sync(0xffffffffu, v, o);
    return v;
}

// =====================================================================
// Kernel 1: fused 1x1 convs (f,g,h) + 2x2 maxpool for f,h.
// Grid: (32 row-pairs, 16 batches), 384 threads.
// Dynamic smem: xs[128][128] (64KB) + ws[96][128] (48KB, reused as cs[80][128])
// =====================================================================
__global__ void __launch_bounds__(384) conv_pool_kernel(
    const float* __restrict__ x,
    const float* __restrict__ Wf, const float* __restrict__ bf,
    const float* __restrict__ Wg, const float* __restrict__ bg,
    const float* __restrict__ Wh, const float* __restrict__ bh)
{
    extern __shared__ float sm1[];
    float* xs = sm1;            // [128][128]  pix-contiguous
    float* ws = sm1 + 16384;    // [96][128]   k rows: 0..15 f, 16..31 g, 32..95 h
    __shared__ float bs[96];

    const int tid = threadIdx.x;
    const int hp  = blockIdx.x;   // pooled row 0..31
    const int b   = blockIdx.y;

    // weights -> smem
    {
        const float4* wf4 = (const float4*)Wf;
        const float4* wg4 = (const float4*)Wg;
        const float4* wh4 = (const float4*)Wh;
        float4* ws4 = (float4*)ws;
        for (int i = tid; i < 512;  i += 384) ws4[i]        = wf4[i];
        for (int i = tid; i < 512;  i += 384) ws4[512 + i]  = wg4[i];
        for (int i = tid; i < 2048; i += 384) ws4[1024 + i] = wh4[i];
        if (tid < 96) bs[tid] = (tid < 16) ? bf[tid] : ((tid < 32) ? bg[tid - 16] : bh[tid - 32]);
    }
    // x slab: rows 2hp, 2hp+1 for all 128 channels; 128 contiguous floats per channel
    {
        float4* xs4 = (float4*)xs;
        for (int i = tid; i < 4096; i += 384) {
            int c = i >> 5, p4 = i & 31;
            xs4[i] = *((const float4*)(x + (size_t)(b * NC + c) * HW + hp * 128) + p4);
        }
    }
    __syncthreads();

    // each thread: 4 consecutive output channels (kq) x 8 pixels (pg)
    const int kq = tid >> 4;        // 0..23
    const int pg = tid & 15;        // 0..15
    const int k0 = kq * 4;
    const int px = pg * 8;

    float acc[4][8];
#pragma unroll
    for (int i = 0; i < 4; i++)
#pragma unroll
        for (int j = 0; j < 8; j++) acc[i][j] = 0.f;

    const float* wr0 = ws + (k0 + 0) * 128;
    const float* wr1 = ws + (k0 + 1) * 128;
    const float* wr2 = ws + (k0 + 2) * 128;
    const float* wr3 = ws + (k0 + 3) * 128;

#pragma unroll 2
    for (int c = 0; c < 128; c += 4) {
        float4 w0 = *(const float4*)(wr0 + c);
        float4 w1 = *(const float4*)(wr1 + c);
        float4 w2 = *(const float4*)(wr2 + c);
        float4 w3 = *(const float4*)(wr3 + c);
        float wa0[4] = {w0.x, w0.y, w0.z, w0.w};
        float wa1[4] = {w1.x, w1.y, w1.z, w1.w};
        float wa2[4] = {w2.x, w2.y, w2.z, w2.w};
        float wa3[4] = {w3.x, w3.y, w3.z, w3.w};
#pragma unroll
        for (int ci = 0; ci < 4; ci++) {
            float4 xa = *(const float4*)(xs + (c + ci) * 128 + px);
            float4 xb = *(const float4*)(xs + (c + ci) * 128 + px + 4);
            float xv[8] = {xa.x, xa.y, xa.z, xa.w, xb.x, xb.y, xb.z, xb.w};
#pragma unroll
            for (int j = 0; j < 8; j++) {
                acc[0][j] = fmaf(wa0[ci], xv[j], acc[0][j]);
                acc[1][j] = fmaf(wa1[ci], xv[j], acc[1][j]);
                acc[2][j] = fmaf(wa2[ci], xv[j], acc[2][j]);
                acc[3][j] = fmaf(wa3[ci], xv[j], acc[3][j]);
            }
        }
    }
    __syncthreads();   // done with xs & ws reads; ws region reused as cs below

    const int r    = pg >> 3;         // row within pair
    const int colb = (pg & 7) * 8;    // column base (0..56)

    if (kq >= 4 && kq < 8) {
        // g channels: full resolution, write directly
#pragma unroll
        for (int i = 0; i < 4; i++) {
            const int k = k0 + i;                 // 16..31
            const float bias = bs[k];
            float* gp = g_g + (size_t)(b * K8 + (k - 16)) * HW + (2 * hp + r) * 64 + colb;
            *(float4*)gp       = make_float4(acc[i][0] + bias, acc[i][1] + bias,
                                             acc[i][2] + bias, acc[i][3] + bias);
            *(float4*)(gp + 4) = make_float4(acc[i][4] + bias, acc[i][5] + bias,
                                             acc[i][6] + bias, acc[i][7] + bias);
        }
    } else {
        // f (k<16) and h (k>=32) channels: stage in smem for pooling
        float* cs = ws;   // [80][128]: 0..15 f, 16..79 h
#pragma unroll
        for (int i = 0; i < 4; i++) {
            const int k = k0 + i;
            const int kfh = (k < 16) ? k : (k - 16);
            const float bias = bs[k];
            float* dst = cs + kfh * 128 + px;
            *(float4*)dst       = make_float4(acc[i][0] + bias, acc[i][1] + bias,
                                              acc[i][2] + bias, acc[i][3] + bias);
            *(float4*)(dst + 4) = make_float4(acc[i][4] + bias, acc[i][5] + bias,
                                              acc[i][6] + bias, acc[i][7] + bias);
        }
    }
    __syncthreads();

    // 2x2 maxpool and writeout: 80 channels x 32 pooled cols
    for (int idx = tid; idx < 2560; idx += 384) {
        int k = idx >> 5, wc = idx & 31;
        const float* csr = ws + k * 128;
        float mv = fmaxf(fmaxf(csr[2 * wc], csr[2 * wc + 1]),
                         fmaxf(csr[64 + 2 * wc], csr[64 + 2 * wc + 1]));
        int m = hp * 32 + wc;
        if (k < 16) g_f[(size_t)(b * K8 + k) * MP + m]        = mv;
        else        g_v[(size_t)(b * K2 + (k - 16)) * MP + m] = mv;
    }
}

// =====================================================================
// Kernel 2: s = f^T g (K=16) fused with row softmax -> beta.  s never hits HBM.
// Grid: (256 m-groups of 4, 16 batches), 512 threads. Each thread: 4 rows x 8 cols.
// =====================================================================
__global__ void __launch_bounds__(512) s_softmax_kernel()
{
    const int b   = blockIdx.y;
    const int m0  = blockIdx.x * 4;
    const int tid = threadIdx.x;

    __shared__ float fs[16][4];
    __shared__ float red[4][16];

    if (tid < 64)
        fs[tid >> 2][tid & 3] = g_f[(size_t)(b * K8 + (tid >> 2)) * MP + m0 + (tid & 3)];
    __syncthreads();

    const float* gb = g_g + (size_t)b * K8 * HW;
    const int n0 = tid * 4;   // cols [n0,n0+3] and [2048+n0, 2048+n0+3]

    float acc[4][8];
#pragma unroll
    for (int mi = 0; mi < 4; mi++)
#pragma unroll
        for (int j = 0; j < 8; j++) acc[mi][j] = 0.f;

#pragma unroll
    for (int k = 0; k < 16; k++) {
        const float* gk = gb + (size_t)k * HW;
        float4 ga = *(const float4*)(gk + n0);
        float4 gc = *(const float4*)(gk + 2048 + n0);
        float gv[8] = {ga.x, ga.y, ga.z, ga.w, gc.x, gc.y, gc.z, gc.w};
#pragma unroll
        for (int mi = 0; mi < 4; mi++) {
            const float fv = fs[k][mi];
#pragma unroll
            for (int j = 0; j < 8; j++) acc[mi][j] = fmaf(fv, gv[j], acc[mi][j]);
        }
    }

    const int lane = tid & 31, wid = tid >> 5;

    // --- row max ---
    float rmx[4];
#pragma unroll
    for (int mi = 0; mi < 4; mi++) {
        float v = acc[mi][0];
#pragma unroll
        for (int j = 1; j < 8; j++) v = fmaxf(v, acc[mi][j]);
        rmx[mi] = wredmax(v);
    }
    if (lane == 0) {
#pragma unroll
        for (int mi = 0; mi < 4; mi++) red[mi][wid] = rmx[mi];
    }
    __syncthreads();
    float mxf[4];
#pragma unroll
    for (int mi = 0; mi < 4; mi++) {
        float v = red[mi][0];
#pragma unroll
        for (int w2 = 1; w2 < 16; w2++) v = fmaxf(v, red[mi][w2]);
        mxf[mi] = v;
    }
    __syncthreads();   // before reusing red[]

    // --- exp + row sum ---
    float sms[4];
#pragma unroll
    for (int mi = 0; mi < 4; mi++) {
        float s = 0.f;
#pragma unroll
        for (int j = 0; j < 8; j++) {
            acc[mi][j] = __expf(acc[mi][j] - mxf[mi]);
            s += acc[mi][j];
        }
        sms[mi] = wredsum(s);
    }
    if (lane == 0) {
#pragma unroll
        for (int mi = 0; mi < 4; mi++) red[mi][wid] = sms[mi];
    }
    __syncthreads();

#pragma unroll
    for (int mi = 0; mi < 4; mi++) {
        float s = 0.f;
#pragma unroll
        for (int w2 = 0; w2 < 16; w2++) s += red[mi][w2];
        const float inv = 1.0f / s;
        float* bp = g_beta + (size_t)(b * MP + m0 + mi) * HW + n0;
        *(float4*)bp          = make_float4(acc[mi][0] * inv, acc[mi][1] * inv,
                                            acc[mi][2] * inv, acc[mi][3] * inv);
        *(float4*)(bp + 2048) = make_float4(acc[mi][4] * inv, acc[mi][5] * inv,
                                            acc[mi][6] * inv, acc[mi][7] * inv);
    }
}

// =====================================================================
// Kernel 3: o = v @ beta  (64x4096 per batch, K=1024), fused with
// out = gamma*(Wo @ o + bo) + x.
// Grid: (32 column blocks of 128, 16 batches), 256 threads (tx 0..15, ty 0..15).
// Dyn smem: main loop As[32][68] + Bs[32][128]; epilogue Os[64][132] + WoT[64][128].
// =====================================================================
__global__ void __launch_bounds__(256) attn_out_kernel(
    const float* __restrict__ x, const float* __restrict__ Wo,
    const float* __restrict__ bo, const float* __restrict__ gammap,
    float* __restrict__ out)
{
    extern __shared__ float sm3[];
    float* As = sm3;           // [32][68]   (mi, k) with pad
    float* Bs = sm3 + 2176;    // [32][128]  (mi, n)

    const int b   = blockIdx.y;
    const int nb  = blockIdx.x * 128;
    const int tid = threadIdx.x;
    const int tx  = tid & 15, ty = tid >> 4;
    const int miL = tid & 31, kg = tid >> 5;

    const float* vB    = g_v    + (size_t)b * K2 * MP;
    const float* betaB = g_beta + (size_t)b * MP * HW + nb;

    float acc[4][8];
#pragma unroll
    for (int i = 0; i < 4; i++)
#pragma unroll
        for (int j = 0; j < 8; j++) acc[i][j] = 0.f;

    float  rA[8];
    float4 rB[4];

    // prefetch chunk 0
#pragma unroll
    for (int ii = 0; ii < 8; ii++) rA[ii] = vB[(size_t)(kg + ii * 8) * MP + miL];
#pragma unroll
    for (int it = 0; it < 4; it++) {
        int lin = it * 1024 + tid * 4;
        rB[it] = *(const float4*)(betaB + (size_t)(lin >> 7) * HW + (lin & 127));
    }
#pragma unroll
    for (int ii = 0; ii < 8; ii++) As[miL * 68 + kg + ii * 8] = rA[ii];
#pragma unroll
    for (int it = 0; it < 4; it++) *(float4*)(Bs + it * 1024 + tid * 4) = rB[it];
    __syncthreads();

    for (int c = 0; c < 32; c++) {
        const int mcn = (c + 1) * 32;
        if (c < 31) {
#pragma unroll
            for (int ii = 0; ii < 8; ii++)
                rA[ii] = vB[(size_t)(kg + ii * 8) * MP + mcn + miL];
#pragma unroll
            for (int it = 0; it < 4; it++) {
                int lin = it * 1024 + tid * 4;
                rB[it] = *(const float4*)(betaB + (size_t)(mcn + (lin >> 7)) * HW + (lin & 127));
            }
        }
#pragma unroll
        for (int mi = 0; mi < 32; mi++) {
            float4 a  = *(const float4*)(As + mi * 68 + ty * 4);
            float4 b0 = *(const float4*)(Bs + mi * 128 + tx * 8);
            float4 b1 = *(const float4*)(Bs + mi * 128 + tx * 8 + 4);
            float av[4] = {a.x, a.y, a.z, a.w};
            float bv[8] = {b0.x, b0.y, b0.z, b0.w, b1.x, b1.y, b1.z, b1.w};
#pragma unroll
            for (int i = 0; i < 4; i++)
#pragma unroll
                for (int j = 0; j < 8; j++)
                    acc[i][j] = fmaf(av[i], bv[j], acc[i][j]);
        }
        __syncthreads();
        if (c < 31) {
#pragma unroll
            for (int ii = 0; ii < 8; ii++) As[miL * 68 + kg + ii * 8] = rA[ii];
#pragma unroll
            for (int it = 0; it < 4; it++) *(float4*)(Bs + it * 1024 + tid * 4) = rB[it];
            __syncthreads();
        }
    }

    // ---------------- epilogue: out = gamma*(Wo @ o + bo) + x ----------------
    float* Os  = sm3;          // [64][132]
    float* WoT = sm3 + 8448;   // [64][128]  WoT[k][c] = Wo[c][k]

#pragma unroll
    for (int i2 = 0; i2 < 4; i2++) {
        int k = ty * 4 + i2;
        *(float4*)(Os + k * 132 + tx * 8)     = make_float4(acc[i2][0], acc[i2][1],
                                                            acc[i2][2], acc[i2][3]);
        *(float4*)(Os + k * 132 + tx * 8 + 4) = make_float4(acc[i2][4], acc[i2][5],
                                                            acc[i2][6], acc[i2][7]);
    }
    for (int i = tid; i < 8192; i += 256) {
        int k = i >> 7, cc = i & 127;
        WoT[i] = Wo[cc * 64 + k];
    }
    __syncthreads();

    const float gma = *gammap;
    float acc2[8][8];
#pragma unroll
    for (int i = 0; i < 8; i++)
#pragma unroll
        for (int j = 0; j < 8; j++) acc2[i][j] = 0.f;

#pragma unroll 4
    for (int k = 0; k < 64; k++) {
        float4 w0 = *(const float4*)(WoT + k * 128 + ty * 8);
        float4 w1 = *(const float4*)(WoT + k * 128 + ty * 8 + 4);
        float4 o0 = *(const float4*)(Os + k * 132 + tx * 8);
        float4 o1 = *(const float4*)(Os + k * 132 + tx * 8 + 4);
        float wv[8] = {w0.x, w0.y, w0.z, w0.w, w1.x, w1.y, w1.z, w1.w};
        float ov[8] = {o0.x, o0.y, o0.z, o0.w, o1.x, o1.y, o1.z, o1.w};
#pragma unroll
        for (int i = 0; i < 8; i++)
#pragma unroll
            for (int j = 0; j < 8; j++)
                acc2[i][j] = fmaf(wv[i], ov[j], acc2[i][j]);
    }

#pragma unroll
    for (int rr = 0; rr < 8; rr++) {
        const int cc = ty * 8 + rr;
        const float bias = bo[cc];
        const size_t off = (size_t)(b * NC + cc) * HW + nb + tx * 8;
        float4 x0 = *(const float4*)(x + off);
        float4 x1 = *(const float4*)(x + off + 4);
        float4 r0, r1;
        r0.x = fmaf(gma, acc2[rr][0] + bias, x0.x);
        r0.y = fmaf(gma, acc2[rr][1] + bias, x0.y);
        r0.z = fmaf(gma, acc2[rr][2] + bias, x0.z);
        r0.w = fmaf(gma, acc2[rr][3] + bias, x0.w);
        r1.x = fmaf(gma, acc2[rr][4] + bias, x1.x);
        r1.y = fmaf(gma, acc2[rr][5] + bias, x1.y);
        r1.z = fmaf(gma, acc2[rr][6] + bias, x1.z);
        r1.w = fmaf(gma, acc2[rr][7] + bias, x1.w);
        *(float4*)(out + off)     = r0;
        *(float4*)(out + off + 4) = r1;
    }
}

// =====================================================================
extern "C" void kernel_launch(void* const* d_in, const int* in_sizes, int n_in,
                              void* d_out, int out_size)
{
    (void)in_sizes; (void)n_in; (void)out_size;
    const float* x     = (const float*)d_in[0];
    const float* Wf    = (const float*)d_in[1];
    const float* bf    = (const float*)d_in[2];
    const float* Wg    = (const float*)d_in[3];
    const float* bg    = (const float*)d_in[4];
    const float* Wh    = (const float*)d_in[5];
    const float* bh    = (const float*)d_in[6];
    const float* Wo    = (const float*)d_in[7];
    const float* bo    = (const float*)d_in[8];
    const float* gamma = (const float*)d_in[9];
    float* out = (float*)d_out;

    // opt-in large dynamic smem (idempotent; safe under graph capture)
    cudaFuncSetAttribute(conv_pool_kernel,
                         cudaFuncAttributeMaxDynamicSharedMemorySize, 114688);
    cudaFuncSetAttribute(attn_out_kernel,
                         cudaFuncAttributeMaxDynamicSharedMemorySize, 66560);

    conv_pool_kernel<<<dim3(32, NB), 384, 114688>>>(x, Wf, bf, Wg, bg, Wh, bh);
    s_softmax_kernel<<<dim3(256, NB), 512>>>();
    attn_out_kernel<<<dim3(32, NB), 256, 66560>>>(x, Wo, bo, gamma, out);
}

// round 13
// speedup vs baseline: 1.8269x; 1.8254x over previous
#include <cuda_runtime.h>
#include <cstdint>
#include <cstddef>

// Problem constants
#define NB 16
#define NC 128
#define HW 4096          // 64*64
#define MP 1024          // pooled positions (32*32)
#define K8 16            // C/8
#define K2 64            // C/2

// ---------------- scratch (device globals; no allocation allowed) ----------------
__device__ __align__(16) float g_ft[NB * MP * K8];     // f transposed: [b][m][k]
__device__ __align__(16) float g_g [NB * K8 * HW];     // g: [b][k][n]
__device__ __align__(16) float g_v [NB * K2 * MP];     // v: [b][k2][m]
__device__ float g_mx[NB * MP];                        // softmax row max
__device__ float g_iz[NB * MP];                        // softmax 1/Z

// ---------------- helpers ----------------
__device__ __forceinline__ float tf32r(float x) {
    uint32_t u;
    asm("cvt.rna.tf32.f32 %0, %1;" : "=r"(u) : "f"(x));
    return __uint_as_float(u);
}

__device__ __forceinline__ void mma_tf32(float c[4],
                                         uint32_t a0, uint32_t a1, uint32_t a2, uint32_t a3,
                                         uint32_t b0, uint32_t b1) {
    asm volatile("mma.sync.aligned.m16n8k8.row.col.f32.tf32.tf32.f32 "
                 "{%0,%1,%2,%3},{%4,%5,%6,%7},{%8,%9},{%0,%1,%2,%3};"
                 : "+f"(c[0]), "+f"(c[1]), "+f"(c[2]), "+f"(c[3])
                 : "r"(a0), "r"(a1), "r"(a2), "r"(a3), "r"(b0), "r"(b1));
}

// s-tile: 32(m) x 128(n) chunk of s = f^T g, distributed over 8 warps.
// warp w: mhalf = w>>2 (16 rows), ng = w&3 (32 cols; 4 n-tiles of 8).
// gs: [16][136] tf32-rounded g block; fs: [32][20] tf32-rounded f chunk (m-major).
__device__ __forceinline__ void s_tile(const uint32_t* __restrict__ gsu,
                                       const uint32_t* __restrict__ fsu,
                                       int mhalf, int ng, int q, int tig, float sc[4][4]) {
#pragma unroll
    for (int t = 0; t < 4; t++)
#pragma unroll
        for (int j = 0; j < 4; j++) sc[t][j] = 0.f;
    const int m0 = mhalf * 16;
#pragma unroll
    for (int ks = 0; ks < 2; ks++) {
        uint32_t a0 = fsu[(m0 + q)     * 20 + ks * 8 + tig];
        uint32_t a1 = fsu[(m0 + q + 8) * 20 + ks * 8 + tig];
        uint32_t a2 = fsu[(m0 + q)     * 20 + ks * 8 + tig + 4];
        uint32_t a3 = fsu[(m0 + q + 8) * 20 + ks * 8 + tig + 4];
#pragma unroll
        for (int t = 0; t < 4; t++) {
            uint32_t b0 = gsu[(ks * 8 + tig)     * 136 + ng * 32 + t * 8 + q];
            uint32_t b1 = gsu[(ks * 8 + tig + 4) * 136 + ng * 32 + t * 8 + q];
            mma_tf32(sc[t], a0, a1, a2, a3, b0, b1);
        }
    }
}

// =====================================================================
// Kernel 1: fused 1x1 convs (f,g,h) + 2x2 maxpool for f,h. (unchanged
// structure; f now written transposed as g_ft[b][m][k])
// Grid: (32 row-pairs, 16 batches), 384 threads.
// =====================================================================
__global__ void __launch_bounds__(384) conv_pool_kernel(
    const float* __restrict__ x,
    const float* __restrict__ Wf, const float* __restrict__ bf,
    const float* __restrict__ Wg, const float* __restrict__ bg,
    const float* __restrict__ Wh, const float* __restrict__ bh)
{
    extern __shared__ float sm1[];
    float* xs = sm1;            // [128][128]
    float* ws = sm1 + 16384;    // [96][128]
    __shared__ float bs[96];

    const int tid = threadIdx.x;
    const int hp  = blockIdx.x;
    const int b   = blockIdx.y;

    {
        const float4* wf4 = (const float4*)Wf;
        const float4* wg4 = (const float4*)Wg;
        const float4* wh4 = (const float4*)Wh;
        float4* ws4 = (float4*)ws;
        for (int i = tid; i < 512;  i += 384) ws4[i]        = wf4[i];
        for (int i = tid; i < 512;  i += 384) ws4[512 + i]  = wg4[i];
        for (int i = tid; i < 2048; i += 384) ws4[1024 + i] = wh4[i];
        if (tid < 96) bs[tid] = (tid < 16) ? bf[tid] : ((tid < 32) ? bg[tid - 16] : bh[tid - 32]);
    }
    {
        float4* xs4 = (float4*)xs;
        for (int i = tid; i < 4096; i += 384) {
            int c = i >> 5, p4 = i & 31;
            xs4[i] = *((const float4*)(x + (size_t)(b * NC + c) * HW + hp * 128) + p4);
        }
    }
    __syncthreads();

    const int kq = tid >> 4;
    const int pg = tid & 15;
    const int k0 = kq * 4;
    const int px = pg * 8;

    float acc[4][8];
#pragma unroll
    for (int i = 0; i < 4; i++)
#pragma unroll
        for (int j = 0; j < 8; j++) acc[i][j] = 0.f;

    const float* wr0 = ws + (k0 + 0) * 128;
    const float* wr1 = ws + (k0 + 1) * 128;
    const float* wr2 = ws + (k0 + 2) * 128;
    const float* wr3 = ws + (k0 + 3) * 128;

#pragma unroll 2
    for (int c = 0; c < 128; c += 4) {
        float4 w0 = *(const float4*)(wr0 + c);
        float4 w1 = *(const float4*)(wr1 + c);
        float4 w2 = *(const float4*)(wr2 + c);
        float4 w3 = *(const float4*)(wr3 + c);
        float wa0[4] = {w0.x, w0.y, w0.z, w0.w};
        float wa1[4] = {w1.x, w1.y, w1.z, w1.w};
        float wa2[4] = {w2.x, w2.y, w2.z, w2.w};
        float wa3[4] = {w3.x, w3.y, w3.z, w3.w};
#pragma unroll
        for (int ci = 0; ci < 4; ci++) {
            float4 xa = *(const float4*)(xs + (c + ci) * 128 + px);
            float4 xb = *(const float4*)(xs + (c + ci) * 128 + px + 4);
            float xv[8] = {xa.x, xa.y, xa.z, xa.w, xb.x, xb.y, xb.z, xb.w};
#pragma unroll
            for (int j = 0; j < 8; j++) {
                acc[0][j] = fmaf(wa0[ci], xv[j], acc[0][j]);
                acc[1][j] = fmaf(wa1[ci], xv[j], acc[1][j]);
                acc[2][j] = fmaf(wa2[ci], xv[j], acc[2][j]);
                acc[3][j] = fmaf(wa3[ci], xv[j], acc[3][j]);
            }
        }
    }
    __syncthreads();

    const int r    = pg >> 3;
    const int colb = (pg & 7) * 8;

    if (kq >= 4 && kq < 8) {
#pragma unroll
        for (int i = 0; i < 4; i++) {
            const int k = k0 + i;
            const float bias = bs[k];
            float* gp = g_g + (size_t)(b * K8 + (k - 16)) * HW + (2 * hp + r) * 64 + colb;
            *(float4*)gp       = make_float4(acc[i][0] + bias, acc[i][1] + bias,
                                             acc[i][2] + bias, acc[i][3] + bias);
            *(float4*)(gp + 4) = make_float4(acc[i][4] + bias, acc[i][5] + bias,
                                             acc[i][6] + bias, acc[i][7] + bias);
        }
    } else {
        float* cs = ws;
#pragma unroll
        for (int i = 0; i < 4; i++) {
            const int k = k0 + i;
            const int kfh = (k < 16) ? k : (k - 16);
            const float bias = bs[k];
            float* dst = cs + kfh * 128 + px;
            *(float4*)dst       = make_float4(acc[i][0] + bias, acc[i][1] + bias,
                                              acc[i][2] + bias, acc[i][3] + bias);
            *(float4*)(dst + 4) = make_float4(acc[i][4] + bias, acc[i][5] + bias,
                                              acc[i][6] + bias, acc[i][7] + bias);
        }
    }
    __syncthreads();

    for (int idx = tid; idx < 2560; idx += 384) {
        int k = idx >> 5, wc = idx & 31;
        const float* csr = ws + k * 128;
        float mv = fmaxf(fmaxf(csr[2 * wc], csr[2 * wc + 1]),
                         fmaxf(csr[64 + 2 * wc], csr[64 + 2 * wc + 1]));
        int m = hp * 32 + wc;
        if (k < 16) g_ft[((size_t)b * MP + m) * 16 + k]       = mv;   // transposed f
        else        g_v[(size_t)(b * K2 + (k - 16)) * MP + m] = mv;
    }
}

// =====================================================================
// Kernel 2: per-row softmax stats (max, 1/Z) over n=4096 via tf32 mma
// (online softmax). Grid: (32 m-chunks, 16 batches), 256 threads.
// Dyn smem: gs[16][136] + fs[32][20] = 11264 B.
// =====================================================================
__global__ void __launch_bounds__(256) row_stats_kernel()
{
    extern __shared__ float sm2[];
    float* gs = sm2;            // [16][136]
    float* fs = sm2 + 2176;     // [32][20]
    __shared__ float swm[32][4];
    __shared__ float sws[32][4];

    const int b   = blockIdx.y;
    const int mc  = blockIdx.x;
    const int tid = threadIdx.x;
    const int w   = tid >> 5, lane = tid & 31;
    const int q   = lane >> 2, tig = lane & 3;
    const int mhalf = w >> 2, ng = w & 3;

    const uint32_t* gsu = (const uint32_t*)gs;
    const uint32_t* fsu = (const uint32_t*)fs;

    // fs: [m][k] tf32-rounded
    if (tid < 128) {
        float4 v4 = *(const float4*)(g_ft + ((size_t)b * MP + mc * 32) * 16 + tid * 4);
        int m = (tid * 4) >> 4, k = (tid * 4) & 15;
        *(float4*)(fs + m * 20 + k) =
            make_float4(tf32r(v4.x), tf32r(v4.y), tf32r(v4.z), tf32r(v4.w));
    }

    float mx0 = -1e30f, sm0 = 0.f;   // row mhalf*16+q
    float mx1 = -1e30f, sm1 = 0.f;   // row mhalf*16+q+8

    for (int nb = 0; nb < 32; nb++) {
        __syncthreads();
        for (int i = tid; i < 512; i += 256) {
            int lin = i * 4, k = lin >> 7, n = lin & 127;
            float4 v4 = *(const float4*)(g_g + (size_t)(b * K8 + k) * HW + nb * 128 + n);
            *(float4*)(gs + k * 136 + n) =
                make_float4(tf32r(v4.x), tf32r(v4.y), tf32r(v4.z), tf32r(v4.w));
        }
        __syncthreads();

        float sc[4][4];
        s_tile(gsu, fsu, mhalf, ng, q, tig, sc);

        // online softmax update (row0: sc[t][0..1], row1: sc[t][2..3])
        float cm0 = sc[0][0], cm1 = sc[0][2];
#pragma unroll
        for (int t = 0; t < 4; t++) {
            cm0 = fmaxf(cm0, fmaxf(sc[t][0], sc[t][1]));
            cm1 = fmaxf(cm1, fmaxf(sc[t][2], sc[t][3]));
        }
        float nm0 = fmaxf(mx0, cm0), nm1 = fmaxf(mx1, cm1);
        sm0 *= __expf(mx0 - nm0);
        sm1 *= __expf(mx1 - nm1);
#pragma unroll
        for (int t = 0; t < 4; t++) {
            sm0 += __expf(sc[t][0] - nm0) + __expf(sc[t][1] - nm0);
            sm1 += __expf(sc[t][2] - nm1) + __expf(sc[t][3] - nm1);
        }
        mx0 = nm0; mx1 = nm1;
    }

    // quad reduce (lanes sharing q)
#pragma unroll
    for (int off = 1; off <= 2; off <<= 1) {
        float omx = __shfl_xor_sync(0xffffffffu, mx0, off);
        float osm = __shfl_xor_sync(0xffffffffu, sm0, off);
        float nm = fmaxf(mx0, omx);
        sm0 = sm0 * __expf(mx0 - nm) + osm * __expf(omx - nm);
        mx0 = nm;
        omx = __shfl_xor_sync(0xffffffffu, mx1, off);
        osm = __shfl_xor_sync(0xffffffffu, sm1, off);
        nm = fmaxf(mx1, omx);
        sm1 = sm1 * __expf(mx1 - nm) + osm * __expf(omx - nm);
        mx1 = nm;
    }
    if (tig == 0) {
        int lr = mhalf * 16 + q;
        swm[lr][ng] = mx0;     sws[lr][ng] = sm0;
        swm[lr + 8][ng] = mx1; sws[lr + 8][ng] = sm1;
    }
    __syncthreads();
    if (tid < 32) {
        float nm = swm[tid][0];
#pragma unroll
        for (int j = 1; j < 4; j++) nm = fmaxf(nm, swm[tid][j]);
        float Z = 0.f;
#pragma unroll
        for (int j = 0; j < 4; j++) Z += sws[tid][j] * __expf(swm[tid][j] - nm);
        g_mx[(size_t)b * MP + mc * 32 + tid] = nm;
        g_iz[(size_t)b * MP + mc * 32 + tid] = 1.0f / Z;
    }
}

// =====================================================================
// Kernel 3: flash-fused o = v @ softmax(f^T g) with tf32 mma, then
// out = gamma*(Wo @ o + bo) + x.  beta never touches HBM.
// Grid: (32 n-blocks of 128, 16 batches), 256 threads.
// Dyn smem main: gs[16][136] + fs[32][20] + vs[64][36] + bs[32][136] + stats
//               = 9536 floats; epilogue Os[64][132]+WoT[64][128] = 16640 floats.
// =====================================================================
__global__ void __launch_bounds__(256) attn_out_kernel(
    const float* __restrict__ x, const float* __restrict__ Wo,
    const float* __restrict__ bo, const float* __restrict__ gammap,
    float* __restrict__ out)
{
    extern __shared__ float sm3[];
    float* gs  = sm3;            // [16][136]
    float* fs  = sm3 + 2176;     // [32][20]
    float* vs  = sm3 + 2816;     // [64][36]
    float* bsm = sm3 + 5120;     // [32][136]  beta chunk
    float* mxs = sm3 + 9472;     // [32]
    float* izs = sm3 + 9504;     // [32]

    const uint32_t* gsu = (const uint32_t*)gs;
    const uint32_t* fsu = (const uint32_t*)fs;
    const uint32_t* vsu = (const uint32_t*)vs;
    const uint32_t* bsu = (const uint32_t*)bsm;

    const int b   = blockIdx.y;
    const int nb  = blockIdx.x;                 // n-block of 128 cols
    const int tid = threadIdx.x;
    const int w   = tid >> 5, lane = tid & 31;
    const int q   = lane >> 2, tig = lane & 3;
    const int mhalf = w >> 2, ng = w & 3;       // s-phase mapping
    const int r0  = (w >> 1) * 16;              // o-phase rows (64 = 4 groups)
    const int n0o = (w & 1) * 64;               // o-phase cols (2 groups)

    // g block for this CTA's 128 columns (resident all chunks)
    for (int i = tid; i < 512; i += 256) {
        int lin = i * 4, k = lin >> 7, n = lin & 127;
        float4 v4 = *(const float4*)(g_g + (size_t)(b * K8 + k) * HW + nb * 128 + n);
        *(float4*)(gs + k * 136 + n) =
            make_float4(tf32r(v4.x), tf32r(v4.y), tf32r(v4.z), tf32r(v4.w));
    }

    float acc[8][4];
#pragma unroll
    for (int t = 0; t < 8; t++)
#pragma unroll
        for (int j = 0; j < 4; j++) acc[t][j] = 0.f;

    for (int ch = 0; ch < 32; ch++) {
        __syncthreads();   // protect fs/vs/bsm (and first-iter gs) from prior readers

        // loads: fs [32m][16k], vs [64k2][32m], stats [32]
        if (tid < 128) {
            float4 v4 = *(const float4*)(g_ft + ((size_t)b * MP + ch * 32) * 16 + tid * 4);
            int m = (tid * 4) >> 4, k = (tid * 4) & 15;
            *(float4*)(fs + m * 20 + k) =
                make_float4(tf32r(v4.x), tf32r(v4.y), tf32r(v4.z), tf32r(v4.w));
        }
        for (int i = tid; i < 512; i += 256) {
            int lin = i * 4, k2 = lin >> 5, m = lin & 31;
            float4 v4 = *(const float4*)(g_v + (size_t)(b * K2 + k2) * MP + ch * 32 + m);
            *(float4*)(vs + k2 * 36 + m) =
                make_float4(tf32r(v4.x), tf32r(v4.y), tf32r(v4.z), tf32r(v4.w));
        }
        if (tid < 32) {
            mxs[tid] = g_mx[(size_t)b * MP + ch * 32 + tid];
            izs[tid] = g_iz[(size_t)b * MP + ch * 32 + tid];
        }
        __syncthreads();

        // ---- s chunk + exp -> beta in smem ----
        float sc[4][4];
        s_tile(gsu, fsu, mhalf, ng, q, tig, sc);

        const int lr0 = mhalf * 16 + q;
        const float m0v = mxs[lr0],     iz0 = izs[lr0];
        const float m1v = mxs[lr0 + 8], iz1 = izs[lr0 + 8];
#pragma unroll
        for (int t = 0; t < 4; t++) {
            int col = ng * 32 + t * 8 + 2 * tig;
            *(float2*)(bsm + lr0 * 136 + col) =
                make_float2(tf32r(__expf(sc[t][0] - m0v) * iz0),
                            tf32r(__expf(sc[t][1] - m0v) * iz0));
            *(float2*)(bsm + (lr0 + 8) * 136 + col) =
                make_float2(tf32r(__expf(sc[t][2] - m1v) * iz1),
                            tf32r(__expf(sc[t][3] - m1v) * iz1));
        }
        __syncthreads();

        // ---- o accumulate: acc += v_chunk(64x32) @ beta_chunk(32x128) ----
#pragma unroll
        for (int ks = 0; ks < 4; ks++) {
            uint32_t a0 = vsu[(r0 + q)     * 36 + ks * 8 + tig];
            uint32_t a1 = vsu[(r0 + q + 8) * 36 + ks * 8 + tig];
            uint32_t a2 = vsu[(r0 + q)     * 36 + ks * 8 + tig + 4];
            uint32_t a3 = vsu[(r0 + q + 8) * 36 + ks * 8 + tig + 4];
#pragma unroll
            for (int t = 0; t < 8; t++) {
                uint32_t b0 = bsu[(ks * 8 + tig)     * 136 + n0o + t * 8 + q];
                uint32_t b1 = bsu[(ks * 8 + tig + 4) * 136 + n0o + t * 8 + q];
                mma_tf32(acc[t], a0, a1, a2, a3, b0, b1);
            }
        }
    }
    __syncthreads();

    // ---------------- epilogue: out = gamma*(Wo @ o + bo) + x ----------------
    float* Os  = sm3;          // [64][132]
    float* WoT = sm3 + 8448;   // [64][128]

#pragma unroll
    for (int t = 0; t < 8; t++) {
        int col = n0o + t * 8 + 2 * tig;
        *(float2*)(Os + (r0 + q) * 132 + col)     = make_float2(acc[t][0], acc[t][1]);
        *(float2*)(Os + (r0 + q + 8) * 132 + col) = make_float2(acc[t][2], acc[t][3]);
    }
    for (int i = tid; i < 8192; i += 256) {
        int k = i >> 7, cc = i & 127;
        WoT[i] = Wo[cc * 64 + k];
    }
    __syncthreads();

    const int tx = tid & 15, ty = tid >> 4;
    const float gma = *gammap;
    float acc2[8][8];
#pragma unroll
    for (int i = 0; i < 8; i++)
#pragma unroll
        for (int j = 0; j < 8; j++) acc2[i][j] = 0.f;

#pragma unroll 4
    for (int k = 0; k < 64; k++) {
        float4 w0 = *(const float4*)(WoT + k * 128 + ty * 8);
        float4 w1 = *(const float4*)(WoT + k * 128 + ty * 8 + 4);
        float4 o0 = *(const float4*)(Os + k * 132 + tx * 8);
        float4 o1 = *(const float4*)(Os + k * 132 + tx * 8 + 4);
        float wv[8] = {w0.x, w0.y, w0.z, w0.w, w1.x, w1.y, w1.z, w1.w};
        float ov[8] = {o0.x, o0.y, o0.z, o0.w, o1.x, o1.y, o1.z, o1.w};
#pragma unroll
        for (int i = 0; i < 8; i++)
#pragma unroll
            for (int j = 0; j < 8; j++)
                acc2[i][j] = fmaf(wv[i], ov[j], acc2[i][j]);
    }

#pragma unroll
    for (int rr = 0; rr < 8; rr++) {
        const int cc = ty * 8 + rr;
        const float bias = bo[cc];
        const size_t off = (size_t)(b * NC + cc) * HW + nb * 128 + tx * 8;
        float4 x0 = *(const float4*)(x + off);
        float4 x1 = *(const float4*)(x + off + 4);
        float4 rA, rB;
        rA.x = fmaf(gma, acc2[rr][0] + bias, x0.x);
        rA.y = fmaf(gma, acc2[rr][1] + bias, x0.y);
        rA.z = fmaf(gma, acc2[rr][2] + bias, x0.z);
        rA.w = fmaf(gma, acc2[rr][3] + bias, x0.w);
        rB.x = fmaf(gma, acc2[rr][4] + bias, x1.x);
        rB.y = fmaf(gma, acc2[rr][5] + bias, x1.y);
        rB.z = fmaf(gma, acc2[rr][6] + bias, x1.z);
        rB.w = fmaf(gma, acc2[rr][7] + bias, x1.w);
        *(float4*)(out + off)     = rA;
        *(float4*)(out + off + 4) = rB;
    }
}

// =====================================================================
extern "C" void kernel_launch(void* const* d_in, const int* in_sizes, int n_in,
                              void* d_out, int out_size)
{
    (void)in_sizes; (void)n_in; (void)out_size;
    const float* x     = (const float*)d_in[0];
    const float* Wf    = (const float*)d_in[1];
    const float* bf    = (const float*)d_in[2];
    const float* Wg    = (const float*)d_in[3];
    const float* bg    = (const float*)d_in[4];
    const float* Wh    = (const float*)d_in[5];
    const float* bh    = (const float*)d_in[6];
    const float* Wo    = (const float*)d_in[7];
    const float* bo    = (const float*)d_in[8];
    const float* gamma = (const float*)d_in[9];
    float* out = (float*)d_out;

    cudaFuncSetAttribute(conv_pool_kernel,
                         cudaFuncAttributeMaxDynamicSharedMemorySize, 114688);
    cudaFuncSetAttribute(attn_out_kernel,
                         cudaFuncAttributeMaxDynamicSharedMemorySize, 66560);

    conv_pool_kernel<<<dim3(32, NB), 384, 114688>>>(x, Wf, bf, Wg, bg, Wh, bh);
    row_stats_kernel<<<dim3(32, NB), 256, 11264>>>();
    attn_out_kernel<<<dim3(32, NB), 256, 66560>>>(x, Wo, bo, gamma, out);
}

// round 14
// speedup vs baseline: 1.9040x; 1.0422x over previous
#include <cuda_runtime.h>
#include <cuda_bf16.h>
#include <cstdint>
#include <cstddef>

// Problem constants
#define NB 16
#define NC 128
#define HW 4096          // 64*64
#define MP 1024          // pooled positions (32*32)
#define K8 16            // C/8
#define K2 64            // C/2

// ---------------- scratch (device globals; no allocation allowed) ----------------
__device__ __align__(16) float    g_ft[NB * MP * K8];          // f transposed: [b][m][k]
__device__ __align__(16) float    g_g [NB * K8 * HW];          // g: [b][k][n]
__device__ __align__(16) float    g_v [NB * K2 * MP];          // v: [b][k2][m]
__device__ __align__(16) uint16_t g_be[(size_t)NB * MP * HW];  // exp(s) bf16: [b][m][n] 134MB
__device__ float g_iz[NB * MP];                                // 1/Z per row

// ---------------- helpers ----------------
__device__ __forceinline__ float tf32r(float x) {
    uint32_t u;
    asm("cvt.rna.tf32.f32 %0, %1;" : "=r"(u) : "f"(x));
    return __uint_as_float(u);
}

__device__ __forceinline__ void mma_tf32(float c[4],
                                         uint32_t a0, uint32_t a1, uint32_t a2, uint32_t a3,
                                         uint32_t b0, uint32_t b1) {
    asm volatile("mma.sync.aligned.m16n8k8.row.col.f32.tf32.tf32.f32 "
                 "{%0,%1,%2,%3},{%4,%5,%6,%7},{%8,%9},{%0,%1,%2,%3};"
                 : "+f"(c[0]), "+f"(c[1]), "+f"(c[2]), "+f"(c[3])
                 : "r"(a0), "r"(a1), "r"(a2), "r"(a3), "r"(b0), "r"(b1));
}

// s-tile: 32(m) x 128(n) chunk of s = f^T g, distributed over 8 warps.
__device__ __forceinline__ void s_tile(const uint32_t* __restrict__ gsu,
                                       const uint32_t* __restrict__ fsu,
                                       int mhalf, int ng, int q, int tig, float sc[4][4]) {
#pragma unroll
    for (int t = 0; t < 4; t++)
#pragma unroll
        for (int j = 0; j < 4; j++) sc[t][j] = 0.f;
    const int m0 = mhalf * 16;
#pragma unroll
    for (int ks = 0; ks < 2; ks++) {
        uint32_t a0 = fsu[(m0 + q)     * 20 + ks * 8 + tig];
        uint32_t a1 = fsu[(m0 + q + 8) * 20 + ks * 8 + tig];
        uint32_t a2 = fsu[(m0 + q)     * 20 + ks * 8 + tig + 4];
        uint32_t a3 = fsu[(m0 + q + 8) * 20 + ks * 8 + tig + 4];
#pragma unroll
        for (int t = 0; t < 4; t++) {
            uint32_t b0 = gsu[(ks * 8 + tig)     * 136 + ng * 32 + t * 8 + q];
            uint32_t b1 = gsu[(ks * 8 + tig + 4) * 136 + ng * 32 + t * 8 + q];
            mma_tf32(sc[t], a0, a1, a2, a3, b0, b1);
        }
    }
}

// =====================================================================
// Kernel 1: fused 1x1 convs (f,g,h) + 2x2 maxpool for f,h. (unchanged)
// =====================================================================
__global__ void __launch_bounds__(384) conv_pool_kernel(
    const float* __restrict__ x,
    const float* __restrict__ Wf, const float* __restrict__ bf,
    const float* __restrict__ Wg, const float* __restrict__ bg,
    const float* __restrict__ Wh, const float* __restrict__ bh)
{
    extern __shared__ float sm1[];
    float* xs = sm1;            // [128][128]
    float* ws = sm1 + 16384;    // [96][128]
    __shared__ float bs[96];

    const int tid = threadIdx.x;
    const int hp  = blockIdx.x;
    const int b   = blockIdx.y;

    {
        const float4* wf4 = (const float4*)Wf;
        const float4* wg4 = (const float4*)Wg;
        const float4* wh4 = (const float4*)Wh;
        float4* ws4 = (float4*)ws;
        for (int i = tid; i < 512;  i += 384) ws4[i]        = wf4[i];
        for (int i = tid; i < 512;  i += 384) ws4[512 + i]  = wg4[i];
        for (int i = tid; i < 2048; i += 384) ws4[1024 + i] = wh4[i];
        if (tid < 96) bs[tid] = (tid < 16) ? bf[tid] : ((tid < 32) ? bg[tid - 16] : bh[tid - 32]);
    }
    {
        float4* xs4 = (float4*)xs;
        for (int i = tid; i < 4096; i += 384) {
            int c = i >> 5, p4 = i & 31;
            xs4[i] = *((const float4*)(x + (size_t)(b * NC + c) * HW + hp * 128) + p4);
        }
    }
    __syncthreads();

    const int kq = tid >> 4;
    const int pg = tid & 15;
    const int k0 = kq * 4;
    const int px = pg * 8;

    float acc[4][8];
#pragma unroll
    for (int i = 0; i < 4; i++)
#pragma unroll
        for (int j = 0; j < 8; j++) acc[i][j] = 0.f;

    const float* wr0 = ws + (k0 + 0) * 128;
    const float* wr1 = ws + (k0 + 1) * 128;
    const float* wr2 = ws + (k0 + 2) * 128;
    const float* wr3 = ws + (k0 + 3) * 128;

#pragma unroll 2
    for (int c = 0; c < 128; c += 4) {
        float4 w0 = *(const float4*)(wr0 + c);
        float4 w1 = *(const float4*)(wr1 + c);
        float4 w2 = *(const float4*)(wr2 + c);
        float4 w3 = *(const float4*)(wr3 + c);
        float wa0[4] = {w0.x, w0.y, w0.z, w0.w};
        float wa1[4] = {w1.x, w1.y, w1.z, w1.w};
        float wa2[4] = {w2.x, w2.y, w2.z, w2.w};
        float wa3[4] = {w3.x, w3.y, w3.z, w3.w};
#pragma unroll
        for (int ci = 0; ci < 4; ci++) {
            float4 xa = *(const float4*)(xs + (c + ci) * 128 + px);
            float4 xb = *(const float4*)(xs + (c + ci) * 128 + px + 4);
            float xv[8] = {xa.x, xa.y, xa.z, xa.w, xb.x, xb.y, xb.z, xb.w};
#pragma unroll
            for (int j = 0; j < 8; j++) {
                acc[0][j] = fmaf(wa0[ci], xv[j], acc[0][j]);
                acc[1][j] = fmaf(wa1[ci], xv[j], acc[1][j]);
                acc[2][j] = fmaf(wa2[ci], xv[j], acc[2][j]);
                acc[3][j] = fmaf(wa3[ci], xv[j], acc[3][j]);
            }
        }
    }
    __syncthreads();

    const int r    = pg >> 3;
    const int colb = (pg & 7) * 8;

    if (kq >= 4 && kq < 8) {
#pragma unroll
        for (int i = 0; i < 4; i++) {
            const int k = k0 + i;
            const float bias = bs[k];
            float* gp = g_g + (size_t)(b * K8 + (k - 16)) * HW + (2 * hp + r) * 64 + colb;
            *(float4*)gp       = make_float4(acc[i][0] + bias, acc[i][1] + bias,
                                             acc[i][2] + bias, acc[i][3] + bias);
            *(float4*)(gp + 4) = make_float4(acc[i][4] + bias, acc[i][5] + bias,
                                             acc[i][6] + bias, acc[i][7] + bias);
        }
    } else {
        float* cs = ws;
#pragma unroll
        for (int i = 0; i < 4; i++) {
            const int k = k0 + i;
            const int kfh = (k < 16) ? k : (k - 16);
            const float bias = bs[k];
            float* dst = cs + kfh * 128 + px;
            *(float4*)dst       = make_float4(acc[i][0] + bias, acc[i][1] + bias,
                                              acc[i][2] + bias, acc[i][3] + bias);
            *(float4*)(dst + 4) = make_float4(acc[i][4] + bias, acc[i][5] + bias,
                                              acc[i][6] + bias, acc[i][7] + bias);
        }
    }
    __syncthreads();

    for (int idx = tid; idx < 2560; idx += 384) {
        int k = idx >> 5, wc = idx & 31;
        const float* csr = ws + k * 128;
        float mv = fmaxf(fmaxf(csr[2 * wc], csr[2 * wc + 1]),
                         fmaxf(csr[64 + 2 * wc], csr[64 + 2 * wc + 1]));
        int m = hp * 32 + wc;
        if (k < 16) g_ft[((size_t)b * MP + m) * 16 + k]       = mv;
        else        g_v[(size_t)(b * K2 + (k - 16)) * MP + m] = mv;
    }
}

// =====================================================================
// Kernel 2: s = f^T g via tf32 mma; writes expE = exp(s) as bf16 (no max
// subtraction needed: |s| << 88) + per-row 1/Z.
// Grid: (32 m-chunks, 16 batches), 256 threads.
// =====================================================================
__global__ void __launch_bounds__(256) stats_exp_kernel()
{
    __shared__ float    gs[16 * 136];
    __shared__ float    fs[32 * 20];
    __shared__ unsigned bes[32 * 68];   // bf16x2-packed exp chunk [32 rows][64 pairs]+pad
    __shared__ float    sws[32][4];

    const int b   = blockIdx.y;
    const int mc  = blockIdx.x;
    const int tid = threadIdx.x;
    const int w   = tid >> 5, lane = tid & 31;
    const int q   = lane >> 2, tig = lane & 3;
    const int mhalf = w >> 2, ng = w & 3;
    const int lr0 = mhalf * 16 + q;

    const uint32_t* gsu = (const uint32_t*)gs;
    const uint32_t* fsu = (const uint32_t*)fs;

    if (tid < 128) {
        float4 v4 = *(const float4*)(g_ft + ((size_t)b * MP + mc * 32) * 16 + tid * 4);
        int m = (tid * 4) >> 4, k = (tid * 4) & 15;
        *(float4*)(fs + m * 20 + k) =
            make_float4(tf32r(v4.x), tf32r(v4.y), tf32r(v4.z), tf32r(v4.w));
    }

    float sm0 = 0.f, sm1 = 0.f;

    for (int nb = 0; nb < 32; nb++) {
        __syncthreads();
        for (int i = tid; i < 512; i += 256) {
            int lin = i * 4, k = lin >> 7, n = lin & 127;
            float4 v4 = *(const float4*)(g_g + (size_t)(b * K8 + k) * HW + nb * 128 + n);
            *(float4*)(gs + k * 136 + n) =
                make_float4(tf32r(v4.x), tf32r(v4.y), tf32r(v4.z), tf32r(v4.w));
        }
        __syncthreads();

        float sc[4][4];
        s_tile(gsu, fsu, mhalf, ng, q, tig, sc);

#pragma unroll
        for (int t = 0; t < 4; t++) {
            float e0 = __expf(sc[t][0]), e1 = __expf(sc[t][1]);
            float e2 = __expf(sc[t][2]), e3 = __expf(sc[t][3]);
            sm0 += e0 + e1;
            sm1 += e2 + e3;
            __nv_bfloat162 p0 = __floats2bfloat162_rn(e0, e1);
            __nv_bfloat162 p1 = __floats2bfloat162_rn(e2, e3);
            int ci = ng * 16 + t * 4 + tig;
            bes[lr0 * 68 + ci]       = *(unsigned*)&p0;
            bes[(lr0 + 8) * 68 + ci] = *(unsigned*)&p1;
        }
        __syncthreads();

        // coalesced store: 32 rows x 128 bf16
        {
            int m = tid >> 3, cg = tid & 7;
            uint4 v0 = *(const uint4*)(bes + m * 68 + cg * 8);
            uint4 v1 = *(const uint4*)(bes + m * 68 + cg * 8 + 4);
            uint4* dst = (uint4*)(g_be + ((size_t)b * MP + mc * 32 + m) * HW + nb * 128 + cg * 16);
            dst[0] = v0;
            dst[1] = v1;
        }
    }

    // Z reduce: quad (tig) then across ng warps
    sm0 += __shfl_xor_sync(0xffffffffu, sm0, 1);
    sm0 += __shfl_xor_sync(0xffffffffu, sm0, 2);
    sm1 += __shfl_xor_sync(0xffffffffu, sm1, 1);
    sm1 += __shfl_xor_sync(0xffffffffu, sm1, 2);
    if (tig == 0) {
        sws[lr0][ng]     = sm0;
        sws[lr0 + 8][ng] = sm1;
    }
    __syncthreads();
    if (tid < 32) {
        float Z = sws[tid][0] + sws[tid][1] + sws[tid][2] + sws[tid][3];
        g_iz[(size_t)b * MP + mc * 32 + tid] = 1.0f / Z;
    }
}

// =====================================================================
// Kernel 3: o = (v * 1/Z) @ expE  (tf32 mma, expE bf16->f32 exact), then
// out = gamma*(Wo @ o + bo) + x.
// Grid: (32 n-blocks of 128, 16 batches), 256 threads, 8 warps in 2x4
// (warp tile 32 k2-rows x 32 cols). Register-prefetch double buffering.
// Dyn smem main: vs[64][36] + bsm[32][136] = 6656 f; epilogue 16640 f.
// =====================================================================
__global__ void __launch_bounds__(256) attn_out_kernel(
    const float* __restrict__ x, const float* __restrict__ Wo,
    const float* __restrict__ bo, const float* __restrict__ gammap,
    float* __restrict__ out)
{
    extern __shared__ float sm3[];
    float* vs  = sm3;           // [64][36]
    float* bsm = sm3 + 2304;    // [32][136]
    const uint32_t* vsu = (const uint32_t*)vs;
    const uint32_t* bsu = (const uint32_t*)bsm;

    const int b   = blockIdx.y;
    const int nb  = blockIdx.x;
    const int tid = threadIdx.x;
    const int w   = tid >> 5, lane = tid & 31;
    const int q   = lane >> 2, tig = lane & 3;
    const int rw  = w >> 2, cw = w & 3;          // 2x4 warp grid

    const float*    vB  = g_v  + (size_t)b * K2 * MP;
    const float*    izB = g_iz + (size_t)b * MP;
    const uint16_t* beB = g_be + (size_t)b * MP * HW + nb * 128;

    const int k2a  = tid >> 3;          // 0..31  (v row, also expE row)
    const int mofs = (tid & 7) * 4;     // v m-offset
    const int colb = (tid & 7) * 16;    // expE col base

    float4 rv0, rv1, riz;
    uint4  re0, re1;

    // prefetch chunk 0
    rv0 = *(const float4*)(vB + (size_t)k2a * MP + mofs);
    rv1 = *(const float4*)(vB + (size_t)(k2a + 32) * MP + mofs);
    riz = *(const float4*)(izB + mofs);
    {
        const uint16_t* bp = beB + (size_t)k2a * HW + colb;
        re0 = *(const uint4*)bp;
        re1 = *(const uint4*)(bp + 8);
    }

    float acc[2][4][4];
#pragma unroll
    for (int mt = 0; mt < 2; mt++)
#pragma unroll
        for (int t = 0; t < 4; t++)
#pragma unroll
            for (int j = 0; j < 4; j++) acc[mt][t][j] = 0.f;

    for (int ch = 0; ch < 32; ch++) {
        // ---- stage current chunk from regs into smem ----
        *(float4*)(vs + k2a * 36 + mofs) =
            make_float4(tf32r(rv0.x * riz.x), tf32r(rv0.y * riz.y),
                        tf32r(rv0.z * riz.z), tf32r(rv0.w * riz.w));
        *(float4*)(vs + (k2a + 32) * 36 + mofs) =
            make_float4(tf32r(rv1.x * riz.x), tf32r(rv1.y * riz.y),
                        tf32r(rv1.z * riz.z), tf32r(rv1.w * riz.w));
        {
            unsigned ua[8] = {re0.x, re0.y, re0.z, re0.w, re1.x, re1.y, re1.z, re1.w};
            float fb[16];
#pragma unroll
            for (int j = 0; j < 8; j++) {
                fb[2 * j]     = __uint_as_float(ua[j] << 16);        // bf16 -> f32 exact
                fb[2 * j + 1] = __uint_as_float(ua[j] & 0xffff0000u);
            }
#pragma unroll
            for (int s4 = 0; s4 < 4; s4++)
                *(float4*)(bsm + k2a * 136 + colb + s4 * 4) = *(float4*)(fb + s4 * 4);
        }
        __syncthreads();

        // ---- prefetch next chunk ----
        if (ch < 31) {
            int c2 = (ch + 1) * 32;
            rv0 = *(const float4*)(vB + (size_t)k2a * MP + c2 + mofs);
            rv1 = *(const float4*)(vB + (size_t)(k2a + 32) * MP + c2 + mofs);
            riz = *(const float4*)(izB + c2 + mofs);
            const uint16_t* bp = beB + (size_t)(c2 + k2a) * HW + colb;
            re0 = *(const uint4*)bp;
            re1 = *(const uint4*)(bp + 8);
        }

        // ---- MMA: acc += v'(64x32) @ expE(32x128) ----
#pragma unroll
        for (int ks = 0; ks < 4; ks++) {
            uint32_t A[2][4];
#pragma unroll
            for (int mt = 0; mt < 2; mt++) {
                int rb = rw * 32 + mt * 16;
                A[mt][0] = vsu[(rb + q)     * 36 + ks * 8 + tig];
                A[mt][1] = vsu[(rb + q + 8) * 36 + ks * 8 + tig];
                A[mt][2] = vsu[(rb + q)     * 36 + ks * 8 + tig + 4];
                A[mt][3] = vsu[(rb + q + 8) * 36 + ks * 8 + tig + 4];
            }
#pragma unroll
            for (int t = 0; t < 4; t++) {
                uint32_t b0 = bsu[(ks * 8 + tig)     * 136 + cw * 32 + t * 8 + q];
                uint32_t b1 = bsu[(ks * 8 + tig + 4) * 136 + cw * 32 + t * 8 + q];
                mma_tf32(acc[0][t], A[0][0], A[0][1], A[0][2], A[0][3], b0, b1);
                mma_tf32(acc[1][t], A[1][0], A[1][1], A[1][2], A[1][3], b0, b1);
            }
        }
        __syncthreads();
    }

    // ---------------- epilogue: out = gamma*(Wo @ o + bo) + x ----------------
    float* Os  = sm3;          // [64][132]
    float* WoT = sm3 + 8448;   // [64][128]

#pragma unroll
    for (int mt = 0; mt < 2; mt++)
#pragma unroll
        for (int t = 0; t < 4; t++) {
            int rr = rw * 32 + mt * 16 + q;
            int cc = cw * 32 + t * 8 + 2 * tig;
            *(float2*)(Os + rr * 132 + cc)       = make_float2(acc[mt][t][0], acc[mt][t][1]);
            *(float2*)(Os + (rr + 8) * 132 + cc) = make_float2(acc[mt][t][2], acc[mt][t][3]);
        }
    for (int i = tid; i < 8192; i += 256) {
        int k = i >> 7, cc = i & 127;
        WoT[i] = Wo[cc * 64 + k];
    }
    __syncthreads();

    const int tx = tid & 15, ty = tid >> 4;
    const float gma = *gammap;
    float acc2[8][8];
#pragma unroll
    for (int i = 0; i < 8; i++)
#pragma unroll
        for (int j = 0; j < 8; j++) acc2[i][j] = 0.f;

#pragma unroll 4
    for (int k = 0; k < 64; k++) {
        float4 w0 = *(const float4*)(WoT + k * 128 + ty * 8);
        float4 w1 = *(const float4*)(WoT + k * 128 + ty * 8 + 4);
        float4 o0 = *(const float4*)(Os + k * 132 + tx * 8);
        float4 o1 = *(const float4*)(Os + k * 132 + tx * 8 + 4);
        float wv[8] = {w0.x, w0.y, w0.z, w0.w, w1.x, w1.y, w1.z, w1.w};
        float ov[8] = {o0.x, o0.y, o0.z, o0.w, o1.x, o1.y, o1.z, o1.w};
#pragma unroll
        for (int i = 0; i < 8; i++)
#pragma unroll
            for (int j = 0; j < 8; j++)
                acc2[i][j] = fmaf(wv[i], ov[j], acc2[i][j]);
    }

#pragma unroll
    for (int rr = 0; rr < 8; rr++) {
        const int cc = ty * 8 + rr;
        const float bias = bo[cc];
        const size_t off = (size_t)(b * NC + cc) * HW + nb * 128 + tx * 8;
        float4 x0 = *(const float4*)(x + off);
        float4 x1 = *(const float4*)(x + off + 4);
        float4 rA, rB;
        rA.x = fmaf(gma, acc2[rr][0] + bias, x0.x);
        rA.y = fmaf(gma, acc2[rr][1] + bias, x0.y);
        rA.z = fmaf(gma, acc2[rr][2] + bias, x0.z);
        rA.w = fmaf(gma, acc2[rr][3] + bias, x0.w);
        rB.x = fmaf(gma, acc2[rr][4] + bias, x1.x);
        rB.y = fmaf(gma, acc2[rr][5] + bias, x1.y);
        rB.z = fmaf(gma, acc2[rr][6] + bias, x1.z);
        rB.w = fmaf(gma, acc2[rr][7] + bias, x1.w);
        *(float4*)(out + off)     = rA;
        *(float4*)(out + off + 4) = rB;
    }
}

// =====================================================================
extern "C" void kernel_launch(void* const* d_in, const int* in_sizes, int n_in,
                              void* d_out, int out_size)
{
    (void)in_sizes; (void)n_in; (void)out_size;
    const float* x     = (const float*)d_in[0];
    const float* Wf    = (const float*)d_in[1];
    const float* bf    = (const float*)d_in[2];
    const float* Wg    = (const float*)d_in[3];
    const float* bg    = (const float*)d_in[4];
    const float* Wh    = (const float*)d_in[5];
    const float* bh    = (const float*)d_in[6];
    const float* Wo    = (const float*)d_in[7];
    const float* bo    = (const float*)d_in[8];
    const float* gamma = (const float*)d_in[9];
    float* out = (float*)d_out;

    cudaFuncSetAttribute(conv_pool_kernel,
                         cudaFuncAttributeMaxDynamicSharedMemorySize, 114688);
    cudaFuncSetAttribute(attn_out_kernel,
                         cudaFuncAttributeMaxDynamicSharedMemorySize, 66560);

    conv_pool_kernel<<<dim3(32, NB), 384, 114688>>>(x, Wf, bf, Wg, bg, Wh, bh);
    stats_exp_kernel<<<dim3(32, NB), 256>>>();
    attn_out_kernel<<<dim3(32, NB), 256, 66560>>>(x, Wo, bo, gamma, out);
}

// round 15
// speedup vs baseline: 2.0538x; 1.0787x over previous
#include <cuda_runtime.h>
#include <cuda_bf16.h>
#include <cstdint>
#include <cstddef>

// Problem constants
#define NB 16
#define NC 128
#define HW 4096          // 64*64
#define MP 1024          // pooled positions (32*32)
#define K8 16            // C/8
#define K2 64            // C/2

// ---------------- scratch (device globals; no allocation allowed) ----------------
__device__ __align__(16) float    g_ft[NB * MP * K8];          // f transposed: [b][m][k]
__device__ __align__(16) float    g_g [NB * K8 * HW];          // g: [b][k][n]
__device__ __align__(16) float    g_v [NB * K2 * MP];          // v: [b][k2][m]
__device__ __align__(16) uint16_t g_be[(size_t)NB * MP * HW];  // exp(s) bf16: [b][m][n]
__device__ float g_iz[NB * MP];                                // 1/Z per row

// ---------------- helpers ----------------
__device__ __forceinline__ float tf32r(float x) {
    uint32_t u;
    asm("cvt.rna.tf32.f32 %0, %1;" : "=r"(u) : "f"(x));
    return __uint_as_float(u);
}

__device__ __forceinline__ void mma_tf32(float c[4],
                                         uint32_t a0, uint32_t a1, uint32_t a2, uint32_t a3,
                                         uint32_t b0, uint32_t b1) {
    asm volatile("mma.sync.aligned.m16n8k8.row.col.f32.tf32.tf32.f32 "
                 "{%0,%1,%2,%3},{%4,%5,%6,%7},{%8,%9},{%0,%1,%2,%3};"
                 : "+f"(c[0]), "+f"(c[1]), "+f"(c[2]), "+f"(c[3])
                 : "r"(a0), "r"(a1), "r"(a2), "r"(a3), "r"(b0), "r"(b1));
}

// s-tile: 32(m) x 128(n) chunk of s = f^T g, distributed over 8 warps.
__device__ __forceinline__ void s_tile(const uint32_t* __restrict__ gsu,
                                       const uint32_t* __restrict__ fsu,
                                       int mhalf, int ng, int q, int tig, float sc[4][4]) {
#pragma unroll
    for (int t = 0; t < 4; t++)
#pragma unroll
        for (int j = 0; j < 4; j++) sc[t][j] = 0.f;
    const int m0 = mhalf * 16;
#pragma unroll
    for (int ks = 0; ks < 2; ks++) {
        uint32_t a0 = fsu[(m0 + q)     * 20 + ks * 8 + tig];
        uint32_t a1 = fsu[(m0 + q + 8) * 20 + ks * 8 + tig];
        uint32_t a2 = fsu[(m0 + q)     * 20 + ks * 8 + tig + 4];
        uint32_t a3 = fsu[(m0 + q + 8) * 20 + ks * 8 + tig + 4];
#pragma unroll
        for (int t = 0; t < 4; t++) {
            uint32_t b0 = gsu[(ks * 8 + tig)     * 136 + ng * 32 + t * 8 + q];
            uint32_t b1 = gsu[(ks * 8 + tig + 4) * 136 + ng * 32 + t * 8 + q];
            mma_tf32(sc[t], a0, a1, a2, a3, b0, b1);
        }
    }
}

// =====================================================================
// Kernel 1: fused 1x1 convs (f,g,h) via tf32 mma + 2x2 maxpool for f,h.
// Per CTA: M=96 (16 f / 16 g / 64 h) x N=128 px x K=128 ch.
// Grid: (32 row-pairs, 16 batches), 256 threads (8 warps, 2x4 grid).
// Dyn smem: as[96][132] (weights, then conv out) + xs[128][136] = 120320 B.
// =====================================================================
__global__ void __launch_bounds__(256) conv_pool_kernel(
    const float* __restrict__ x,
    const float* __restrict__ Wf, const float* __restrict__ bf,
    const float* __restrict__ Wg, const float* __restrict__ bg,
    const float* __restrict__ Wh, const float* __restrict__ bh)
{
    extern __shared__ float sm1[];
    float* as = sm1;            // [96][132]  A = W (tf32); later conv output
    float* xs = sm1 + 12672;    // [128][136] B = x slab (tf32)
    __shared__ float bs[96];

    const int tid  = threadIdx.x;
    const int hp   = blockIdx.x;
    const int b    = blockIdx.y;
    const int w    = tid >> 5, lane = tid & 31;
    const int q    = lane >> 2, tig = lane & 3;
    const int rw   = w >> 2, cw = w & 3;        // 2x4 warp grid
    const int mb   = rw * 48, nb0 = cw * 32;

    const uint32_t* asu = (const uint32_t*)as;
    const uint32_t* xsu = (const uint32_t*)xs;

    // weights -> smem (tf32), rows 0..15 f, 16..31 g, 32..95 h
    for (int i = tid; i < 3072; i += 256) {
        int lin = i * 4, m = lin >> 7, k = lin & 127;
        const float* src = (m < 16) ? (Wf + m * 128 + k)
                         : (m < 32) ? (Wg + (m - 16) * 128 + k)
                                    : (Wh + (m - 32) * 128 + k);
        float4 v4 = *(const float4*)src;
        *(float4*)(as + m * 132 + k) =
            make_float4(tf32r(v4.x), tf32r(v4.y), tf32r(v4.z), tf32r(v4.w));
    }
    if (tid < 96)
        bs[tid] = (tid < 16) ? bf[tid] : ((tid < 32) ? bg[tid - 16] : bh[tid - 32]);

    // x slab -> smem (tf32): 128 ch x 128 px (rows 2hp, 2hp+1)
    for (int i = tid; i < 4096; i += 256) {
        int lin = i * 4, c = lin >> 7, p = lin & 127;
        float4 v4 = *(const float4*)(x + (size_t)(b * NC + c) * HW + hp * 128 + p);
        *(float4*)(xs + c * 136 + p) =
            make_float4(tf32r(v4.x), tf32r(v4.y), tf32r(v4.z), tf32r(v4.w));
    }
    __syncthreads();

    float acc[3][4][4];
#pragma unroll
    for (int mt = 0; mt < 3; mt++)
#pragma unroll
        for (int nt = 0; nt < 4; nt++)
#pragma unroll
            for (int j = 0; j < 4; j++) acc[mt][nt][j] = 0.f;

#pragma unroll 4
    for (int ks = 0; ks < 16; ks++) {
        uint32_t A[3][4];
#pragma unroll
        for (int mt = 0; mt < 3; mt++) {
            int r0 = mb + mt * 16;
            A[mt][0] = asu[(r0 + q)     * 132 + ks * 8 + tig];
            A[mt][1] = asu[(r0 + q + 8) * 132 + ks * 8 + tig];
            A[mt][2] = asu[(r0 + q)     * 132 + ks * 8 + tig + 4];
            A[mt][3] = asu[(r0 + q + 8) * 132 + ks * 8 + tig + 4];
        }
#pragma unroll
        for (int nt = 0; nt < 4; nt++) {
            uint32_t b0 = xsu[(ks * 8 + tig)     * 136 + nb0 + nt * 8 + q];
            uint32_t b1 = xsu[(ks * 8 + tig + 4) * 136 + nb0 + nt * 8 + q];
#pragma unroll
            for (int mt = 0; mt < 3; mt++)
                mma_tf32(acc[mt][nt], A[mt][0], A[mt][1], A[mt][2], A[mt][3], b0, b1);
        }
    }
    __syncthreads();   // all reads of as/xs complete

    // conv output (+bias) into cs = as region: [96][132]
    float* cs = as;
#pragma unroll
    for (int mt = 0; mt < 3; mt++) {
        int m0 = mb + mt * 16 + q, m1 = m0 + 8;
        float b0v = bs[m0], b1v = bs[m1];
#pragma unroll
        for (int nt = 0; nt < 4; nt++) {
            int cc = nb0 + nt * 8 + 2 * tig;
            *(float2*)(cs + m0 * 132 + cc) = make_float2(acc[mt][nt][0] + b0v,
                                                         acc[mt][nt][1] + b0v);
            *(float2*)(cs + m1 * 132 + cc) = make_float2(acc[mt][nt][2] + b1v,
                                                         acc[mt][nt][3] + b1v);
        }
    }
    __syncthreads();

    // g rows (16..31): full-res store
    for (int i = tid; i < 512; i += 256) {
        int lin = i * 4, kk = lin >> 7, p = lin & 127;
        float4 v4 = *(const float4*)(cs + (16 + kk) * 132 + p);
        *(float4*)(g_g + (size_t)(b * K8 + kk) * HW + hp * 128 + p) = v4;
    }
    // f (rows 0..15) and h (rows 32..95): 2x2 maxpool
    for (int idx = tid; idx < 2560; idx += 256) {
        int k = idx >> 5, wc = idx & 31;
        int row = (k < 16) ? k : (k + 16);
        const float* cr = cs + row * 132;
        float mv = fmaxf(fmaxf(cr[2 * wc], cr[2 * wc + 1]),
                         fmaxf(cr[64 + 2 * wc], cr[64 + 2 * wc + 1]));
        int m = hp * 32 + wc;
        if (k < 16) g_ft[((size_t)b * MP + m) * 16 + k]       = mv;
        else        g_v[(size_t)(b * K2 + (k - 16)) * MP + m] = mv;
    }
}

// =====================================================================
// Kernel 2: s = f^T g via tf32 mma; writes expE = exp(s) as bf16 (no max
// subtraction needed: |s| << 88) + per-row 1/Z.
// Grid: (32 m-chunks, 16 batches), 256 threads.
// =====================================================================
__global__ void __launch_bounds__(256) stats_exp_kernel()
{
    __shared__ float    gs[16 * 136];
    __shared__ float    fs[32 * 20];
    __shared__ unsigned bes[32 * 68];   // bf16x2-packed exp chunk
    __shared__ float    sws[32][4];

    const int b   = blockIdx.y;
    const int mc  = blockIdx.x;
    const int tid = threadIdx.x;
    const int w   = tid >> 5, lane = tid & 31;
    const int q   = lane >> 2, tig = lane & 3;
    const int mhalf = w >> 2, ng = w & 3;
    const int lr0 = mhalf * 16 + q;

    const uint32_t* gsu = (const uint32_t*)gs;
    const uint32_t* fsu = (const uint32_t*)fs;

    if (tid < 128) {
        float4 v4 = *(const float4*)(g_ft + ((size_t)b * MP + mc * 32) * 16 + tid * 4);
        int m = (tid * 4) >> 4, k = (tid * 4) & 15;
        *(float4*)(fs + m * 20 + k) =
            make_float4(tf32r(v4.x), tf32r(v4.y), tf32r(v4.z), tf32r(v4.w));
    }

    float sm0 = 0.f, sm1 = 0.f;

    for (int nb = 0; nb < 32; nb++) {
        __syncthreads();
        for (int i = tid; i < 512; i += 256) {
            int lin = i * 4, k = lin >> 7, n = lin & 127;
            float4 v4 = *(const float4*)(g_g + (size_t)(b * K8 + k) * HW + nb * 128 + n);
            *(float4*)(gs + k * 136 + n) =
                make_float4(tf32r(v4.x), tf32r(v4.y), tf32r(v4.z), tf32r(v4.w));
        }
        __syncthreads();

        float sc[4][4];
        s_tile(gsu, fsu, mhalf, ng, q, tig, sc);

#pragma unroll
        for (int t = 0; t < 4; t++) {
            float e0 = __expf(sc[t][0]), e1 = __expf(sc[t][1]);
            float e2 = __expf(sc[t][2]), e3 = __expf(sc[t][3]);
            sm0 += e0 + e1;
            sm1 += e2 + e3;
            __nv_bfloat162 p0 = __floats2bfloat162_rn(e0, e1);
            __nv_bfloat162 p1 = __floats2bfloat162_rn(e2, e3);
            int ci = ng * 16 + t * 4 + tig;
            bes[lr0 * 68 + ci]       = *(unsigned*)&p0;
            bes[(lr0 + 8) * 68 + ci] = *(unsigned*)&p1;
        }
        __syncthreads();

        {
            int m = tid >> 3, cg = tid & 7;
            uint4 v0 = *(const uint4*)(bes + m * 68 + cg * 8);
            uint4 v1 = *(const uint4*)(bes + m * 68 + cg * 8 + 4);
            uint4* dst = (uint4*)(g_be + ((size_t)b * MP + mc * 32 + m) * HW + nb * 128 + cg * 16);
            dst[0] = v0;
            dst[1] = v1;
        }
    }

    sm0 += __shfl_xor_sync(0xffffffffu, sm0, 1);
    sm0 += __shfl_xor_sync(0xffffffffu, sm0, 2);
    sm1 += __shfl_xor_sync(0xffffffffu, sm1, 1);
    sm1 += __shfl_xor_sync(0xffffffffu, sm1, 2);
    if (tig == 0) {
        sws[lr0][ng]     = sm0;
        sws[lr0 + 8][ng] = sm1;
    }
    __syncthreads();
    if (tid < 32) {
        float Z = sws[tid][0] + sws[tid][1] + sws[tid][2] + sws[tid][3];
        g_iz[(size_t)b * MP + mc * 32 + tid] = 1.0f / Z;
    }
}

// =====================================================================
// Kernel 3: o = (v * 1/Z) @ expE  (tf32 mma, expE bf16->f32 exact), then
// out = gamma*(Wo @ o + bo) + x.
// Grid: (32 n-blocks of 128, 16 batches), 256 threads, 8 warps in 2x4.
// =====================================================================
__global__ void __launch_bounds__(256) attn_out_kernel(
    const float* __restrict__ x, const float* __restrict__ Wo,
    const float* __restrict__ bo, const float* __restrict__ gammap,
    float* __restrict__ out)
{
    extern __shared__ float sm3[];
    float* vs  = sm3;           // [64][36]
    float* bsm = sm3 + 2304;    // [32][136]
    const uint32_t* vsu = (const uint32_t*)vs;
    const uint32_t* bsu = (const uint32_t*)bsm;

    const int b   = blockIdx.y;
    const int nb  = blockIdx.x;
    const int tid = threadIdx.x;
    const int w   = tid >> 5, lane = tid & 31;
    const int q   = lane >> 2, tig = lane & 3;
    const int rw  = w >> 2, cw = w & 3;

    const float*    vB  = g_v  + (size_t)b * K2 * MP;
    const float*    izB = g_iz + (size_t)b * MP;
    const uint16_t* beB = g_be + (size_t)b * MP * HW + nb * 128;

    const int k2a  = tid >> 3;
    const int mofs = (tid & 7) * 4;
    const int colb = (tid & 7) * 16;

    float4 rv0, rv1, riz;
    uint4  re0, re1;

    rv0 = *(const float4*)(vB + (size_t)k2a * MP + mofs);
    rv1 = *(const float4*)(vB + (size_t)(k2a + 32) * MP + mofs);
    riz = *(const float4*)(izB + mofs);
    {
        const uint16_t* bp = beB + (size_t)k2a * HW + colb;
        re0 = *(const uint4*)bp;
        re1 = *(const uint4*)(bp + 8);
    }

    float acc[2][4][4];
#pragma unroll
    for (int mt = 0; mt < 2; mt++)
#pragma unroll
        for (int t = 0; t < 4; t++)
#pragma unroll
            for (int j = 0; j < 4; j++) acc[mt][t][j] = 0.f;

    for (int ch = 0; ch < 32; ch++) {
        *(float4*)(vs + k2a * 36 + mofs) =
            make_float4(tf32r(rv0.x * riz.x), tf32r(rv0.y * riz.y),
                        tf32r(rv0.z * riz.z), tf32r(rv0.w * riz.w));
        *(float4*)(vs + (k2a + 32) * 36 + mofs) =
            make_float4(tf32r(rv1.x * riz.x), tf32r(rv1.y * riz.y),
                        tf32r(rv1.z * riz.z), tf32r(rv1.w * riz.w));
        {
            unsigned ua[8] = {re0.x, re0.y, re0.z, re0.w, re1.x, re1.y, re1.z, re1.w};
            float fb[16];
#pragma unroll
            for (int j = 0; j < 8; j++) {
                fb[2 * j]     = __uint_as_float(ua[j] << 16);
                fb[2 * j + 1] = __uint_as_float(ua[j] & 0xffff0000u);
            }
#pragma unroll
            for (int s4 = 0; s4 < 4; s4++)
                *(float4*)(bsm + k2a * 136 + colb + s4 * 4) = *(float4*)(fb + s4 * 4);
        }
        __syncthreads();

        if (ch < 31) {
            int c2 = (ch + 1) * 32;
            rv0 = *(const float4*)(vB + (size_t)k2a * MP + c2 + mofs);
            rv1 = *(const float4*)(vB + (size_t)(k2a + 32) * MP + c2 + mofs);
            riz = *(const float4*)(izB + c2 + mofs);
            const uint16_t* bp = beB + (size_t)(c2 + k2a) * HW + colb;
            re0 = *(const uint4*)bp;
            re1 = *(const uint4*)(bp + 8);
        }

#pragma unroll
        for (int ks = 0; ks < 4; ks++) {
            uint32_t A[2][4];
#pragma unroll
            for (int mt = 0; mt < 2; mt++) {
                int rb = rw * 32 + mt * 16;
                A[mt][0] = vsu[(rb + q)     * 36 + ks * 8 + tig];
                A[mt][1] = vsu[(rb + q + 8) * 36 + ks * 8 + tig];
                A[mt][2] = vsu[(rb + q)     * 36 + ks * 8 + tig + 4];
                A[mt][3] = vsu[(rb + q + 8) * 36 + ks * 8 + tig + 4];
            }
#pragma unroll
            for (int t = 0; t < 4; t++) {
                uint32_t b0 = bsu[(ks * 8 + tig)     * 136 + cw * 32 + t * 8 + q];
                uint32_t b1 = bsu[(ks * 8 + tig + 4) * 136 + cw * 32 + t * 8 + q];
                mma_tf32(acc[0][t], A[0][0], A[0][1], A[0][2], A[0][3], b0, b1);
                mma_tf32(acc[1][t], A[1][0], A[1][1], A[1][2], A[1][3], b0, b1);
            }
        }
        __syncthreads();
    }

    // ---------------- epilogue: out = gamma*(Wo @ o + bo) + x ----------------
    float* Os  = sm3;          // [64][132]
    float* WoT = sm3 + 8448;   // [64][128]

#pragma unroll
    for (int mt = 0; mt < 2; mt++)
#pragma unroll
        for (int t = 0; t < 4; t++) {
            int rr = rw * 32 + mt * 16 + q;
            int cc = cw * 32 + t * 8 + 2 * tig;
            *(float2*)(Os + rr * 132 + cc)       = make_float2(acc[mt][t][0], acc[mt][t][1]);
            *(float2*)(Os + (rr + 8) * 132 + cc) = make_float2(acc[mt][t][2], acc[mt][t][3]);
        }
    for (int i = tid; i < 8192; i += 256) {
        int k = i >> 7, cc = i & 127;
        WoT[i] = Wo[cc * 64 + k];
    }
    __syncthreads();

    const int tx = tid & 15, ty = tid >> 4;
    const float gma = *gammap;
    float acc2[8][8];
#pragma unroll
    for (int i = 0; i < 8; i++)
#pragma unroll
        for (int j = 0; j < 8; j++) acc2[i][j] = 0.f;

#pragma unroll 4
    for (int k = 0; k < 64; k++) {
        float4 w0 = *(const float4*)(WoT + k * 128 + ty * 8);
        float4 w1 = *(const float4*)(WoT + k * 128 + ty * 8 + 4);
        float4 o0 = *(const float4*)(Os + k * 132 + tx * 8);
        float4 o1 = *(const float4*)(Os + k * 132 + tx * 8 + 4);
        float wv[8] = {w0.x, w0.y, w0.z, w0.w, w1.x, w1.y, w1.z, w1.w};
        float ov[8] = {o0.x, o0.y, o0.z, o0.w, o1.x, o1.y, o1.z, o1.w};
#pragma unroll
        for (int i = 0; i < 8; i++)
#pragma unroll
            for (int j = 0; j < 8; j++)
                acc2[i][j] = fmaf(wv[i], ov[j], acc2[i][j]);
    }

#pragma unroll
    for (int rr = 0; rr < 8; rr++) {
        const int cc = ty * 8 + rr;
        const float bias = bo[cc];
        const size_t off = (size_t)(b * NC + cc) * HW + nb * 128 + tx * 8;
        float4 x0 = *(const float4*)(x + off);
        float4 x1 = *(const float4*)(x + off + 4);
        float4 rA, rB;
        rA.x = fmaf(gma, acc2[rr][0] + bias, x0.x);
        rA.y = fmaf(gma, acc2[rr][1] + bias, x0.y);
        rA.z = fmaf(gma, acc2[rr][2] + bias, x0.z);
        rA.w = fmaf(gma, acc2[rr][3] + bias, x0.w);
        rB.x = fmaf(gma, acc2[rr][4] + bias, x1.x);
        rB.y = fmaf(gma, acc2[rr][5] + bias, x1.y);
        rB.z = fmaf(gma, acc2[rr][6] + bias, x1.z);
        rB.w = fmaf(gma, acc2[rr][7] + bias, x1.w);
        *(float4*)(out + off)     = rA;
        *(float4*)(out + off + 4) = rB;
    }
}

// =====================================================================
extern "C" void kernel_launch(void* const* d_in, const int* in_sizes, int n_in,
                              void* d_out, int out_size)
{
    (void)in_sizes; (void)n_in; (void)out_size;
    const float* x     = (const float*)d_in[0];
    const float* Wf    = (const float*)d_in[1];
    const float* bf    = (const float*)d_in[2];
    const float* Wg    = (const float*)d_in[3];
    const float* bg    = (const float*)d_in[4];
    const float* Wh    = (const float*)d_in[5];
    const float* bh    = (const float*)d_in[6];
    const float* Wo    = (const float*)d_in[7];
    const float* bo    = (const float*)d_in[8];
    const float* gamma = (const float*)d_in[9];
    float* out = (float*)d_out;

    cudaFuncSetAttribute(conv_pool_kernel,
                         cudaFuncAttributeMaxDynamicSharedMemorySize, 120320);
    cudaFuncSetAttribute(attn_out_kernel,
                         cudaFuncAttributeMaxDynamicSharedMemorySize, 66560);

    conv_pool_kernel<<<dim3(32, NB), 256, 120320>>>(x, Wf, bf, Wg, bg, Wh, bh);
    stats_exp_kernel<<<dim3(32, NB), 256>>>();
    attn_out_kernel<<<dim3(32, NB), 256, 66560>>>(x, Wo, bo, gamma, out);
}

// round 16
// speedup vs baseline: 3.0984x; 1.5086x over previous
#include <cuda_runtime.h>
#include <cuda_bf16.h>
#include <cstdint>
#include <cstddef>

// Problem constants
#define NB 16
#define NC 128
#define HW 4096          // 64*64
#define MP 1024          // pooled positions (32*32)
#define K8 16            // C/8
#define K2 64            // C/2

// ---------------- scratch (device globals; no allocation allowed) ----------------
__device__ __align__(16) float    g_ft[NB * MP * K8];          // f transposed: [b][m][k]
__device__ __align__(16) float    g_g [NB * K8 * HW];          // g: [b][k][n] f32
__device__ __align__(16) float    g_v [NB * K2 * MP];          // v: [b][k2][m] f32
__device__ __align__(16) uint16_t g_vb[NB * K2 * MP];          // v' = bf16(v * 1/Z[m])
__device__ __align__(16) uint16_t g_be[(size_t)NB * MP * HW];  // exp(s) bf16: [b][m][n]

// ---------------- helpers ----------------
__device__ __forceinline__ float tf32r(float x) {
    uint32_t u;
    asm("cvt.rna.tf32.f32 %0, %1;" : "=r"(u) : "f"(x));
    return __uint_as_float(u);
}

__device__ __forceinline__ void cpa16(uint32_t d, const void* s) {
    asm volatile("cp.async.cg.shared.global [%0], [%1], 16;" :: "r"(d), "l"(s));
}
__device__ __forceinline__ void cp_commit() {
    asm volatile("cp.async.commit_group;");
}
template <int N>
__device__ __forceinline__ void cp_wait() {
    asm volatile("cp.async.wait_group %0;" :: "n"(N));
}

__device__ __forceinline__ void mma_tf32(float c[4],
                                         uint32_t a0, uint32_t a1, uint32_t a2, uint32_t a3,
                                         uint32_t b0, uint32_t b1) {
    asm volatile("mma.sync.aligned.m16n8k8.row.col.f32.tf32.tf32.f32 "
                 "{%0,%1,%2,%3},{%4,%5,%6,%7},{%8,%9},{%0,%1,%2,%3};"
                 : "+f"(c[0]), "+f"(c[1]), "+f"(c[2]), "+f"(c[3])
                 : "r"(a0), "r"(a1), "r"(a2), "r"(a3), "r"(b0), "r"(b1));
}

__device__ __forceinline__ void mma_bf16(float c[4],
                                         uint32_t a0, uint32_t a1, uint32_t a2, uint32_t a3,
                                         uint32_t b0, uint32_t b1) {
    asm volatile("mma.sync.aligned.m16n8k16.row.col.f32.bf16.bf16.f32 "
                 "{%0,%1,%2,%3},{%4,%5,%6,%7},{%8,%9},{%0,%1,%2,%3};"
                 : "+f"(c[0]), "+f"(c[1]), "+f"(c[2]), "+f"(c[3])
                 : "r"(a0), "r"(a1), "r"(a2), "r"(a3), "r"(b0), "r"(b1));
}

__device__ __forceinline__ void ldm4(uint32_t r[4], uint32_t a) {
    asm volatile("ldmatrix.sync.aligned.m8n8.x4.shared.b16 {%0,%1,%2,%3},[%4];"
                 : "=r"(r[0]), "=r"(r[1]), "=r"(r[2]), "=r"(r[3]) : "r"(a));
}
__device__ __forceinline__ void ldm4t(uint32_t r[4], uint32_t a) {
    asm volatile("ldmatrix.sync.aligned.m8n8.x4.trans.shared.b16 {%0,%1,%2,%3},[%4];"
                 : "=r"(r[0]), "=r"(r[1]), "=r"(r[2]), "=r"(r[3]) : "r"(a));
}

// s-tile: 32(m) x 128(n) chunk of s = f^T g (tf32 mma), 8 warps.
__device__ __forceinline__ void s_tile(const uint32_t* __restrict__ gsu,
                                       const uint32_t* __restrict__ fsu,
                                       int mhalf, int ng, int q, int tig, float sc[4][4]) {
#pragma unroll
    for (int t = 0; t < 4; t++)
#pragma unroll
        for (int j = 0; j < 4; j++) sc[t][j] = 0.f;
    const int m0 = mhalf * 16;
#pragma unroll
    for (int ks = 0; ks < 2; ks++) {
        uint32_t a0 = fsu[(m0 + q)     * 20 + ks * 8 + tig];
        uint32_t a1 = fsu[(m0 + q + 8) * 20 + ks * 8 + tig];
        uint32_t a2 = fsu[(m0 + q)     * 20 + ks * 8 + tig + 4];
        uint32_t a3 = fsu[(m0 + q + 8) * 20 + ks * 8 + tig + 4];
#pragma unroll
        for (int t = 0; t < 4; t++) {
            uint32_t b0 = gsu[(ks * 8 + tig)     * 136 + ng * 32 + t * 8 + q];
            uint32_t b1 = gsu[(ks * 8 + tig + 4) * 136 + ng * 32 + t * 8 + q];
            mma_tf32(sc[t], a0, a1, a2, a3, b0, b1);
        }
    }
}

// =====================================================================
// Kernel 1: fused 1x1 convs (f,g,h) via tf32 mma + 2x2 maxpool.
// x slab loaded raw via cp.async (HW truncates B operand to tf32).
// Grid: (32 row-pairs, 16 batches), 256 threads (8 warps, 2x4 grid).
// =====================================================================
__global__ void __launch_bounds__(256) conv_pool_kernel(
    const float* __restrict__ x,
    const float* __restrict__ Wf, const float* __restrict__ bf,
    const float* __restrict__ Wg, const float* __restrict__ bg,
    const float* __restrict__ Wh, const float* __restrict__ bh)
{
    extern __shared__ float sm1[];
    float* as = sm1;            // [96][132]  A = W (tf32 rna); later conv output
    float* xs = sm1 + 12672;    // [128][136] B = x slab (raw f32)
    __shared__ float bs[96];

    const int tid  = threadIdx.x;
    const int hp   = blockIdx.x;
    const int b    = blockIdx.y;
    const int w    = tid >> 5, lane = tid & 31;
    const int q    = lane >> 2, tig = lane & 3;
    const int rw   = w >> 2, cw = w & 3;
    const int mb   = rw * 48, nb0 = cw * 32;

    const uint32_t* asu = (const uint32_t*)as;
    const uint32_t* xsu = (const uint32_t*)xs;

    // x slab via cp.async (raw)
    {
        uint32_t xsb = (uint32_t)__cvta_generic_to_shared(xs);
#pragma unroll
        for (int it = 0; it < 16; it++) {
            int i = tid + it * 256;                 // 0..4095
            int c = i >> 5, p = (i & 31) * 4;
            cpa16(xsb + (uint32_t)(c * 136 + p) * 4,
                  x + (size_t)(b * NC + c) * HW + hp * 128 + p);
        }
        cp_commit();
    }

    // weights -> smem (tf32 rna)
    for (int i = tid; i < 3072; i += 256) {
        int lin = i * 4, m = lin >> 7, k = lin & 127;
        const float* src = (m < 16) ? (Wf + m * 128 + k)
                         : (m < 32) ? (Wg + (m - 16) * 128 + k)
                                    : (Wh + (m - 32) * 128 + k);
        float4 v4 = *(const float4*)src;
        *(float4*)(as + m * 132 + k) =
            make_float4(tf32r(v4.x), tf32r(v4.y), tf32r(v4.z), tf32r(v4.w));
    }
    if (tid < 96)
        bs[tid] = (tid < 16) ? bf[tid] : ((tid < 32) ? bg[tid - 16] : bh[tid - 32]);

    cp_wait<0>();
    __syncthreads();

    float acc[3][4][4];
#pragma unroll
    for (int mt = 0; mt < 3; mt++)
#pragma unroll
        for (int nt = 0; nt < 4; nt++)
#pragma unroll
            for (int j = 0; j < 4; j++) acc[mt][nt][j] = 0.f;

#pragma unroll 4
    for (int ks = 0; ks < 16; ks++) {
        uint32_t A[3][4];
#pragma unroll
        for (int mt = 0; mt < 3; mt++) {
            int r0 = mb + mt * 16;
            A[mt][0] = asu[(r0 + q)     * 132 + ks * 8 + tig];
            A[mt][1] = asu[(r0 + q + 8) * 132 + ks * 8 + tig];
            A[mt][2] = asu[(r0 + q)     * 132 + ks * 8 + tig + 4];
            A[mt][3] = asu[(r0 + q + 8) * 132 + ks * 8 + tig + 4];
        }
#pragma unroll
        for (int nt = 0; nt < 4; nt++) {
            uint32_t b0 = xsu[(ks * 8 + tig)     * 136 + nb0 + nt * 8 + q];
            uint32_t b1 = xsu[(ks * 8 + tig + 4) * 136 + nb0 + nt * 8 + q];
#pragma unroll
            for (int mt = 0; mt < 3; mt++)
                mma_tf32(acc[mt][nt], A[mt][0], A[mt][1], A[mt][2], A[mt][3], b0, b1);
        }
    }
    __syncthreads();

    // conv output (+bias) into cs = as region: [96][132]
    float* cs = as;
#pragma unroll
    for (int mt = 0; mt < 3; mt++) {
        int m0 = mb + mt * 16 + q, m1 = m0 + 8;
        float b0v = bs[m0], b1v = bs[m1];
#pragma unroll
        for (int nt = 0; nt < 4; nt++) {
            int cc = nb0 + nt * 8 + 2 * tig;
            *(float2*)(cs + m0 * 132 + cc) = make_float2(acc[mt][nt][0] + b0v,
                                                         acc[mt][nt][1] + b0v);
            *(float2*)(cs + m1 * 132 + cc) = make_float2(acc[mt][nt][2] + b1v,
                                                         acc[mt][nt][3] + b1v);
        }
    }
    __syncthreads();

    // g rows (16..31): full-res store
    for (int i = tid; i < 512; i += 256) {
        int lin = i * 4, kk = lin >> 7, p = lin & 127;
        float4 v4 = *(const float4*)(cs + (16 + kk) * 132 + p);
        *(float4*)(g_g + (size_t)(b * K8 + kk) * HW + hp * 128 + p) = v4;
    }
    // f (rows 0..15) and h (rows 32..95): 2x2 maxpool
    for (int idx = tid; idx < 2560; idx += 256) {
        int k = idx >> 5, wc = idx & 31;
        int row = (k < 16) ? k : (k + 16);
        const float* cr = cs + row * 132;
        float mv = fmaxf(fmaxf(cr[2 * wc], cr[2 * wc + 1]),
                         fmaxf(cr[64 + 2 * wc], cr[64 + 2 * wc + 1]));
        int m = hp * 32 + wc;
        if (k < 16) g_ft[((size_t)b * MP + m) * 16 + k]       = mv;
        else        g_v[(size_t)(b * K2 + (k - 16)) * MP + m] = mv;
    }
}

// =====================================================================
// Kernel 2: s = f^T g via tf32 mma; writes expE = exp(s) bf16 + tail
// producing v' = bf16(v * 1/Z). Double-buffered cp.async g pipeline.
// Grid: (32 m-chunks, 16 batches), 256 threads.
// =====================================================================
__global__ void __launch_bounds__(256) stats_exp_kernel()
{
    __shared__ float    gs2[2][16 * 136];   // raw g tiles
    __shared__ float    fs[32 * 20];        // f chunk (tf32 rna)
    __shared__ unsigned bes2[2][32 * 68];   // bf16x2 exp chunks
    __shared__ float    sws[32][4];
    __shared__ float    izv[32];

    const int b   = blockIdx.y;
    const int mc  = blockIdx.x;
    const int tid = threadIdx.x;
    const int w   = tid >> 5, lane = tid & 31;
    const int q   = lane >> 2, tig = lane & 3;
    const int mhalf = w >> 2, ng = w & 3;
    const int lr0 = mhalf * 16 + q;

    const uint32_t* fsu = (const uint32_t*)fs;
    const float* gB = g_g + (size_t)b * K8 * HW;

    // f chunk (rna)
    if (tid < 128) {
        float4 v4 = *(const float4*)(g_ft + ((size_t)b * MP + mc * 32) * 16 + tid * 4);
        int m = (tid * 4) >> 4, k = (tid * 4) & 15;
        *(float4*)(fs + m * 20 + k) =
            make_float4(tf32r(v4.x), tf32r(v4.y), tf32r(v4.z), tf32r(v4.w));
    }

    // issue g tile nb into stage st
    auto issue = [&](int nbv, int st) {
        uint32_t base = (uint32_t)__cvta_generic_to_shared(&gs2[st][0]);
#pragma unroll
        for (int j = 0; j < 2; j++) {
            int i = tid + j * 256;
            int k = i >> 5, c4 = (i & 31) * 4;
            cpa16(base + (uint32_t)(k * 136 + c4) * 4,
                  gB + (size_t)k * HW + nbv * 128 + c4);
        }
        cp_commit();
    };

    issue(0, 0);

    float sm0 = 0.f, sm1 = 0.f;
    const int sm_ = tid >> 3, sc_ = tid & 7;   // for coalesced bes store

    for (int nb = 0; nb < 32; nb++) {
        if (nb < 31) issue(nb + 1, (nb + 1) & 1);
        if (nb < 31) cp_wait<1>(); else cp_wait<0>();
        __syncthreads();   // gs[nb&1] ready; prev packs visible

        if (nb > 0) {
            const unsigned* bp = &bes2[(nb - 1) & 1][0];
            uint4 v0 = *(const uint4*)(bp + sm_ * 68 + sc_ * 8);
            uint4 v1 = *(const uint4*)(bp + sm_ * 68 + sc_ * 8 + 4);
            uint4* dst = (uint4*)(g_be + ((size_t)b * MP + mc * 32 + sm_) * HW
                                  + (nb - 1) * 128 + sc_ * 16);
            dst[0] = v0; dst[1] = v1;
        }

        float sc[4][4];
        s_tile((const uint32_t*)&gs2[nb & 1][0], fsu, mhalf, ng, q, tig, sc);

        unsigned* bcur = &bes2[nb & 1][0];
#pragma unroll
        for (int t = 0; t < 4; t++) {
            float e0 = __expf(sc[t][0]), e1 = __expf(sc[t][1]);
            float e2 = __expf(sc[t][2]), e3 = __expf(sc[t][3]);
            sm0 += e0 + e1;
            sm1 += e2 + e3;
            __nv_bfloat162 p0 = __floats2bfloat162_rn(e0, e1);
            __nv_bfloat162 p1 = __floats2bfloat162_rn(e2, e3);
            int ci = ng * 16 + t * 4 + tig;
            bcur[lr0 * 68 + ci]       = *(unsigned*)&p0;
            bcur[(lr0 + 8) * 68 + ci] = *(unsigned*)&p1;
        }
        __syncthreads();   // gs reads done before reuse; packs before next store
    }

    // final bes store (chunk 31)
    {
        const unsigned* bp = &bes2[1][0];
        uint4 v0 = *(const uint4*)(bp + sm_ * 68 + sc_ * 8);
        uint4 v1 = *(const uint4*)(bp + sm_ * 68 + sc_ * 8 + 4);
        uint4* dst = (uint4*)(g_be + ((size_t)b * MP + mc * 32 + sm_) * HW
                              + 31 * 128 + sc_ * 16);
        dst[0] = v0; dst[1] = v1;
    }

    // Z reduce: quad (tig) then across ng warps
    sm0 += __shfl_xor_sync(0xffffffffu, sm0, 1);
    sm0 += __shfl_xor_sync(0xffffffffu, sm0, 2);
    sm1 += __shfl_xor_sync(0xffffffffu, sm1, 1);
    sm1 += __shfl_xor_sync(0xffffffffu, sm1, 2);
    if (tig == 0) {
        sws[lr0][ng]     = sm0;
        sws[lr0 + 8][ng] = sm1;
    }
    __syncthreads();
    if (tid < 32) {
        float Z = sws[tid][0] + sws[tid][1] + sws[tid][2] + sws[tid][3];
        izv[tid] = 1.0f / Z;
    }
    __syncthreads();

    // v' = bf16(v * 1/Z[m]) for this CTA's 32 m-columns
    for (int i = tid; i < 1024; i += 256) {
        int k2 = i >> 4, m0 = (i & 15) * 2;
        const float* vp = g_v + ((size_t)b * K2 + k2) * MP + mc * 32 + m0;
        float2 vv = *(const float2*)vp;
        __nv_bfloat162 p = __floats2bfloat162_rn(vv.x * izv[m0], vv.y * izv[m0 + 1]);
        *(unsigned*)(g_vb + ((size_t)b * K2 + k2) * MP + mc * 32 + m0) = *(unsigned*)&p;
    }
}

// =====================================================================
// Kernel 3: o = v' @ expE with bf16 mma.m16n8k16 + ldmatrix, then
// out = gamma*(Wo @ o + bo) + x. Double-buffered cp.async pipeline.
// Grid: (32 n-blocks of 128, 16 batches), 256 threads, 8 warps 2x4.
// smem bf16 buffers: vs 2x[64][40] (10240B) + es 2x[32][136] (17408B).
// Epilogue reuses sm3 as Os[64][132] + WoT[64][128] (66560B request).
// =====================================================================
__global__ void __launch_bounds__(256) attn_out_kernel(
    const float* __restrict__ x, const float* __restrict__ Wo,
    const float* __restrict__ bo, const float* __restrict__ gammap,
    float* __restrict__ out)
{
    extern __shared__ float sm3[];
    const uint32_t sb = (uint32_t)__cvta_generic_to_shared(sm3);

    const int b   = blockIdx.y;
    const int nb  = blockIdx.x;
    const int tid = threadIdx.x;
    const int w   = tid >> 5, lane = tid & 31;
    const int q   = lane >> 2, tig = lane & 3;
    const int rw  = w >> 2, cw = w & 3;

    const uint16_t* beB = g_be + (size_t)b * MP * HW + nb * 128;
    const uint16_t* vbB = g_vb + (size_t)b * K2 * MP;

    // ldmatrix lane addressing
    const int lrow  = (lane & 7) + ((lane >> 3) & 1) * 8;
    const int lcol8 = (lane >> 4) * 8;

    // cp.async issue of chunk ch into stage st
    auto issue = [&](int ch, int st) {
        // v' : 64 rows x 32 m (bf16), dst stride 40 bf16 (80B)
        {
            int k2 = tid >> 2, mo = (tid & 3) * 8;
            cpa16(sb + (uint32_t)(st * 5120 + k2 * 80 + (tid & 3) * 16),
                  vbB + (size_t)k2 * MP + ch * 32 + mo);
        }
        // expE : 32 rows x 128 n (bf16), dst stride 136 bf16 (272B)
#pragma unroll
        for (int j = 0; j < 2; j++) {
            int i = tid + j * 256;
            int m = i >> 4, c16 = (i & 15) * 8;
            cpa16(sb + (uint32_t)(10240 + st * 8704 + m * 272 + c16 * 2),
                  beB + (size_t)(ch * 32 + m) * HW + c16);
        }
        cp_commit();
    };

    issue(0, 0);

    float acc[2][4][4];
#pragma unroll
    for (int mt = 0; mt < 2; mt++)
#pragma unroll
        for (int t = 0; t < 4; t++)
#pragma unroll
            for (int j = 0; j < 4; j++) acc[mt][t][j] = 0.f;

    for (int ch = 0; ch < 32; ch++) {
        if (ch < 31) issue(ch + 1, (ch + 1) & 1);
        if (ch < 31) cp_wait<1>(); else cp_wait<0>();
        __syncthreads();

        const uint32_t vbase = sb + (ch & 1) * 5120;
        const uint32_t ebase = sb + 10240 + (ch & 1) * 8704;

#pragma unroll
        for (int ks = 0; ks < 2; ks++) {
            uint32_t A[2][4];
#pragma unroll
            for (int mt = 0; mt < 2; mt++)
                ldm4(A[mt], vbase + (uint32_t)((rw * 32 + mt * 16 + lrow) * 80
                                               + (ks * 16 + lcol8) * 2));
#pragma unroll
            for (int nh = 0; nh < 2; nh++) {
                uint32_t B4[4];
                ldm4t(B4, ebase + (uint32_t)((ks * 16 + lrow) * 272
                                             + (cw * 32 + nh * 16 + lcol8) * 2));
                mma_bf16(acc[0][nh * 2],     A[0][0], A[0][1], A[0][2], A[0][3], B4[0], B4[1]);
                mma_bf16(acc[1][nh * 2],     A[1][0], A[1][1], A[1][2], A[1][3], B4[0], B4[1]);
                mma_bf16(acc[0][nh * 2 + 1], A[0][0], A[0][1], A[0][2], A[0][3], B4[2], B4[3]);
                mma_bf16(acc[1][nh * 2 + 1], A[1][0], A[1][1], A[1][2], A[1][3], B4[2], B4[3]);
            }
        }
        __syncthreads();
    }

    // ---------------- epilogue: out = gamma*(Wo @ o + bo) + x ----------------
    float* Os  = sm3;          // [64][132]
    float* WoT = sm3 + 8448;   // [64][128]

#pragma unroll
    for (int mt = 0; mt < 2; mt++)
#pragma unroll
        for (int t = 0; t < 4; t++) {
            int rr = rw * 32 + mt * 16 + q;
            int cc = cw * 32 + t * 8 + 2 * tig;
            *(float2*)(Os + rr * 132 + cc)       = make_float2(acc[mt][t][0], acc[mt][t][1]);
            *(float2*)(Os + (rr + 8) * 132 + cc) = make_float2(acc[mt][t][2], acc[mt][t][3]);
        }
    for (int i = tid; i < 8192; i += 256) {
        int k = i >> 7, cc = i & 127;
        WoT[i] = Wo[cc * 64 + k];
    }
    __syncthreads();

    const int tx = tid & 15, ty = tid >> 4;
    const float gma = *gammap;
    float acc2[8][8];
#pragma unroll
    for (int i = 0; i < 8; i++)
#pragma unroll
        for (int j = 0; j < 8; j++) acc2[i][j] = 0.f;

#pragma unroll 4
    for (int k = 0; k < 64; k++) {
        float4 w0 = *(const float4*)(WoT + k * 128 + ty * 8);
        float4 w1 = *(const float4*)(WoT + k * 128 + ty * 8 + 4);
        float4 o0 = *(const float4*)(Os + k * 132 + tx * 8);
        float4 o1 = *(const float4*)(Os + k * 132 + tx * 8 + 4);
        float wv[8] = {w0.x, w0.y, w0.z, w0.w, w1.x, w1.y, w1.z, w1.w};
        float ov[8] = {o0.x, o0.y, o0.z, o0.w, o1.x, o1.y, o1.z, o1.w};
#pragma unroll
        for (int i = 0; i < 8; i++)
#pragma unroll
            for (int j = 0; j < 8; j++)
                acc2[i][j] = fmaf(wv[i], ov[j], acc2[i][j]);
    }

#pragma unroll
    for (int rr = 0; rr < 8; rr++) {
        const int cc = ty * 8 + rr;
        const float bias = bo[cc];
        const size_t off = (size_t)(b * NC + cc) * HW + nb * 128 + tx * 8;
        float4 x0 = *(const float4*)(x + off);
        float4 x1 = *(const float4*)(x + off + 4);
        float4 rA, rB;
        rA.x = fmaf(gma, acc2[rr][0] + bias, x0.x);
        rA.y = fmaf(gma, acc2[rr][1] + bias, x0.y);
        rA.z = fmaf(gma, acc2[rr][2] + bias, x0.z);
        rA.w = fmaf(gma, acc2[rr][3] + bias, x0.w);
        rB.x = fmaf(gma, acc2[rr][4] + bias, x1.x);
        rB.y = fmaf(gma, acc2[rr][5] + bias, x1.y);
        rB.z = fmaf(gma, acc2[rr][6] + bias, x1.z);
        rB.w = fmaf(gma, acc2[rr][7] + bias, x1.w);
        *(float4*)(out + off)     = rA;
        *(float4*)(out + off + 4) = rB;
    }
}

// =====================================================================
extern "C" void kernel_launch(void* const* d_in, const int* in_sizes, int n_in,
                              void* d_out, int out_size)
{
    (void)in_sizes; (void)n_in; (void)out_size;
    const float* x     = (const float*)d_in[0];
    const float* Wf    = (const float*)d_in[1];
    const float* bf    = (const float*)d_in[2];
    const float* Wg    = (const float*)d_in[3];
    const float* bg    = (const float*)d_in[4];
    const float* Wh    = (const float*)d_in[5];
    const float* bh    = (const float*)d_in[6];
    const float* Wo    = (const float*)d_in[7];
    const float* bo    = (const float*)d_in[8];
    const float* gamma = (const float*)d_in[9];
    float* out = (float*)d_out;

    cudaFuncSetAttribute(conv_pool_kernel,
                         cudaFuncAttributeMaxDynamicSharedMemorySize, 120320);
    cudaFuncSetAttribute(attn_out_kernel,
                         cudaFuncAttributeMaxDynamicSharedMemorySize, 66560);

    conv_pool_kernel<<<dim3(32, NB), 256, 120320>>>(x, Wf, bf, Wg, bg, Wh, bh);
    stats_exp_kernel<<<dim3(32, NB), 256>>>();
    attn_out_kernel<<<dim3(32, NB), 256, 66560>>>(x, Wo, bo, gamma, out);
}

// round 17
// speedup vs baseline: 3.1935x; 1.0307x over previous
#include <cuda_runtime.h>
#include <cuda_bf16.h>
#include <cstdint>
#include <cstddef>

// Problem constants
#define NB 16
#define NC 128
#define HW 4096          // 64*64
#define MP 1024          // pooled positions (32*32)
#define K8 16            // C/8
#define K2 64            // C/2

// ---------------- scratch (device globals; no allocation allowed) ----------------
__device__ __align__(16) float    g_ft[NB * MP * K8];          // f transposed: [b][m][k]
__device__ __align__(16) float    g_g [NB * K8 * HW];          // g: [b][k][n] f32
__device__ __align__(16) float    g_v [NB * K2 * MP];          // v: [b][k2][m] f32
__device__ __align__(16) uint16_t g_vb[NB * K2 * MP];          // v' = bf16(v * 1/Z[m])
__device__ __align__(16) uint16_t g_be[(size_t)NB * MP * HW];  // exp(s) bf16: [b][m][n]
__device__ __align__(16) float    g_zp[NB * 4 * MP];           // partial Z: [b][nh][m]

// ---------------- helpers ----------------
__device__ __forceinline__ float tf32r(float x) {
    uint32_t u;
    asm("cvt.rna.tf32.f32 %0, %1;" : "=r"(u) : "f"(x));
    return __uint_as_float(u);
}

__device__ __forceinline__ void cpa16(uint32_t d, const void* s) {
    asm volatile("cp.async.cg.shared.global [%0], [%1], 16;" :: "r"(d), "l"(s));
}
__device__ __forceinline__ void cp_commit() {
    asm volatile("cp.async.commit_group;");
}
template <int N>
__device__ __forceinline__ void cp_wait() {
    asm volatile("cp.async.wait_group %0;" :: "n"(N));
}

__device__ __forceinline__ void mma_tf32(float c[4],
                                         uint32_t a0, uint32_t a1, uint32_t a2, uint32_t a3,
                                         uint32_t b0, uint32_t b1) {
    asm volatile("mma.sync.aligned.m16n8k8.row.col.f32.tf32.tf32.f32 "
                 "{%0,%1,%2,%3},{%4,%5,%6,%7},{%8,%9},{%0,%1,%2,%3};"
                 : "+f"(c[0]), "+f"(c[1]), "+f"(c[2]), "+f"(c[3])
                 : "r"(a0), "r"(a1), "r"(a2), "r"(a3), "r"(b0), "r"(b1));
}

__device__ __forceinline__ void mma_bf16(float c[4],
                                         uint32_t a0, uint32_t a1, uint32_t a2, uint32_t a3,
                                         uint32_t b0, uint32_t b1) {
    asm volatile("mma.sync.aligned.m16n8k16.row.col.f32.bf16.bf16.f32 "
                 "{%0,%1,%2,%3},{%4,%5,%6,%7},{%8,%9},{%0,%1,%2,%3};"
                 : "+f"(c[0]), "+f"(c[1]), "+f"(c[2]), "+f"(c[3])
                 : "r"(a0), "r"(a1), "r"(a2), "r"(a3), "r"(b0), "r"(b1));
}

__device__ __forceinline__ void ldm4(uint32_t r[4], uint32_t a) {
    asm volatile("ldmatrix.sync.aligned.m8n8.x4.shared.b16 {%0,%1,%2,%3},[%4];"
                 : "=r"(r[0]), "=r"(r[1]), "=r"(r[2]), "=r"(r[3]) : "r"(a));
}
__device__ __forceinline__ void ldm4t(uint32_t r[4], uint32_t a) {
    asm volatile("ldmatrix.sync.aligned.m8n8.x4.trans.shared.b16 {%0,%1,%2,%3},[%4];"
                 : "=r"(r[0]), "=r"(r[1]), "=r"(r[2]), "=r"(r[3]) : "r"(a));
}

// =====================================================================
// Kernel 1: fused 1x1 convs (f,g,h) via tf32 mma + 2x2 maxpool.
// x slab cp.async in 2 chunks of 64 channels (mma starts at half-load).
// Grid: (32 row-pairs, 16 batches), 256 threads (8 warps, 2x4 grid).
// =====================================================================
__global__ void __launch_bounds__(256) conv_pool_kernel(
    const float* __restrict__ x,
    const float* __restrict__ Wf, const float* __restrict__ bf,
    const float* __restrict__ Wg, const float* __restrict__ bg,
    const float* __restrict__ Wh, const float* __restrict__ bh)
{
    extern __shared__ float sm1[];
    float* as = sm1;            // [96][132]  A = W (tf32 rna); later conv output
    float* xs = sm1 + 12672;    // [128][136] B = x slab (raw f32)
    __shared__ float bs[96];

    const int tid  = threadIdx.x;
    const int hp   = blockIdx.x;
    const int b    = blockIdx.y;
    const int w    = tid >> 5, lane = tid & 31;
    const int q    = lane >> 2, tig = lane & 3;
    const int rw   = w >> 2, cw = w & 3;
    const int mb   = rw * 48, nb0 = cw * 32;

    const uint32_t* asu = (const uint32_t*)as;
    const uint32_t* xsu = (const uint32_t*)xs;

    // x slab via cp.async, 2 chunks of 64 channels
    {
        uint32_t xsb = (uint32_t)__cvta_generic_to_shared(xs);
#pragma unroll
        for (int it = 0; it < 8; it++) {
            int i = tid + it * 256;                 // channels 0..63
            int c = i >> 5, p = (i & 31) * 4;
            cpa16(xsb + (uint32_t)(c * 136 + p) * 4,
                  x + (size_t)(b * NC + c) * HW + hp * 128 + p);
        }
        cp_commit();
#pragma unroll
        for (int it = 8; it < 16; it++) {
            int i = tid + it * 256;                 // channels 64..127
            int c = i >> 5, p = (i & 31) * 4;
            cpa16(xsb + (uint32_t)(c * 136 + p) * 4,
                  x + (size_t)(b * NC + c) * HW + hp * 128 + p);
        }
        cp_commit();
    }

    // weights -> smem (tf32 rna), overlaps x chunk arrival
    for (int i = tid; i < 3072; i += 256) {
        int lin = i * 4, m = lin >> 7, k = lin & 127;
        const float* src = (m < 16) ? (Wf + m * 128 + k)
                         : (m < 32) ? (Wg + (m - 16) * 128 + k)
                                    : (Wh + (m - 32) * 128 + k);
        float4 v4 = *(const float4*)src;
        *(float4*)(as + m * 132 + k) =
            make_float4(tf32r(v4.x), tf32r(v4.y), tf32r(v4.z), tf32r(v4.w));
    }
    if (tid < 96)
        bs[tid] = (tid < 16) ? bf[tid] : ((tid < 32) ? bg[tid - 16] : bh[tid - 32]);

    float acc[3][4][4];
#pragma unroll
    for (int mt = 0; mt < 3; mt++)
#pragma unroll
        for (int nt = 0; nt < 4; nt++)
#pragma unroll
            for (int j = 0; j < 4; j++) acc[mt][nt][j] = 0.f;

    cp_wait<1>();       // chunk0 (channels 0..63) ready
    __syncthreads();

#pragma unroll 4
    for (int ks = 0; ks < 8; ks++) {
        uint32_t A[3][4];
#pragma unroll
        for (int mt = 0; mt < 3; mt++) {
            int r0 = mb + mt * 16;
            A[mt][0] = asu[(r0 + q)     * 132 + ks * 8 + tig];
            A[mt][1] = asu[(r0 + q + 8) * 132 + ks * 8 + tig];
            A[mt][2] = asu[(r0 + q)     * 132 + ks * 8 + tig + 4];
            A[mt][3] = asu[(r0 + q + 8) * 132 + ks * 8 + tig + 4];
        }
#pragma unroll
        for (int nt = 0; nt < 4; nt++) {
            uint32_t b0 = xsu[(ks * 8 + tig)     * 136 + nb0 + nt * 8 + q];
            uint32_t b1 = xsu[(ks * 8 + tig + 4) * 136 + nb0 + nt * 8 + q];
#pragma unroll
            for (int mt = 0; mt < 3; mt++)
                mma_tf32(acc[mt][nt], A[mt][0], A[mt][1], A[mt][2], A[mt][3], b0, b1);
        }
    }

    cp_wait<0>();       // chunk1 ready
    __syncthreads();

#pragma unroll 4
    for (int ks = 8; ks < 16; ks++) {
        uint32_t A[3][4];
#pragma unroll
        for (int mt = 0; mt < 3; mt++) {
            int r0 = mb + mt * 16;
            A[mt][0] = asu[(r0 + q)     * 132 + ks * 8 + tig];
            A[mt][1] = asu[(r0 + q + 8) * 132 + ks * 8 + tig];
            A[mt][2] = asu[(r0 + q)     * 132 + ks * 8 + tig + 4];
            A[mt][3] = asu[(r0 + q + 8) * 132 + ks * 8 + tig + 4];
        }
#pragma unroll
        for (int nt = 0; nt < 4; nt++) {
            uint32_t b0 = xsu[(ks * 8 + tig)     * 136 + nb0 + nt * 8 + q];
            uint32_t b1 = xsu[(ks * 8 + tig + 4) * 136 + nb0 + nt * 8 + q];
#pragma unroll
            for (int mt = 0; mt < 3; mt++)
                mma_tf32(acc[mt][nt], A[mt][0], A[mt][1], A[mt][2], A[mt][3], b0, b1);
        }
    }
    __syncthreads();

    // conv output (+bias) into cs = as region: [96][132]
    float* cs = as;
#pragma unroll
    for (int mt = 0; mt < 3; mt++) {
        int m0 = mb + mt * 16 + q, m1 = m0 + 8;
        float b0v = bs[m0], b1v = bs[m1];
#pragma unroll
        for (int nt = 0; nt < 4; nt++) {
            int cc = nb0 + nt * 8 + 2 * tig;
            *(float2*)(cs + m0 * 132 + cc) = make_float2(acc[mt][nt][0] + b0v,
                                                         acc[mt][nt][1] + b0v);
            *(float2*)(cs + m1 * 132 + cc) = make_float2(acc[mt][nt][2] + b1v,
                                                         acc[mt][nt][3] + b1v);
        }
    }
    __syncthreads();

    // g rows (16..31): full-res store
    for (int i = tid; i < 512; i += 256) {
        int lin = i * 4, kk = lin >> 7, p = lin & 127;
        float4 v4 = *(const float4*)(cs + (16 + kk) * 132 + p);
        *(float4*)(g_g + (size_t)(b * K8 + kk) * HW + hp * 128 + p) = v4;
    }
    // f (rows 0..15) and h (rows 32..95): 2x2 maxpool
    for (int idx = tid; idx < 2560; idx += 256) {
        int k = idx >> 5, wc = idx & 31;
        int row = (k < 16) ? k : (k + 16);
        const float* cr = cs + row * 132;
        float mv = fmaxf(fmaxf(cr[2 * wc], cr[2 * wc + 1]),
                         fmaxf(cr[64 + 2 * wc], cr[64 + 2 * wc + 1]));
        int m = hp * 32 + wc;
        if (k < 16) g_ft[((size_t)b * MP + m) * 16 + k]       = mv;
        else        g_v[(size_t)(b * K2 + (k - 16)) * MP + m] = mv;
    }
}

// =====================================================================
// Kernel 2: s = f^T g via tf32 mma; expE = exp(s) bf16 + partial Z.
// n-sweep split 4 ways: grid (32 m-chunks, 4 n-quarters, 16 batches),
// 8 chunks/CTA, 4-stage cp.async pipeline, one barrier per chunk.
// Dyn smem: gs 4x[16][136] + fs[32][20] + bes 2x[32][68] = 54784 B.
// =====================================================================
__global__ void __launch_bounds__(256) stats_exp_kernel()
{
    extern __shared__ float sm2[];
    float*    gs  = sm2;             // 4 stages x 2176 floats
    float*    fs  = sm2 + 8704;      // [32][20]
    unsigned* bes = (unsigned*)(sm2 + 9344);  // 2 x [32][68]
    __shared__ float sws[32][4];

    const int b   = blockIdx.z;
    const int mc  = blockIdx.x;
    const int nh  = blockIdx.y;      // n-quarter (8 chunks of 128)
    const int tid = threadIdx.x;
    const int w   = tid >> 5, lane = tid & 31;
    const int q   = lane >> 2, tig = lane & 3;
    const int mhalf = w >> 2, ng = w & 3;
    const int lr0 = mhalf * 16 + q;

    const uint32_t* fsu = (const uint32_t*)fs;
    const float* gB = g_g + (size_t)b * K8 * HW;
    const uint32_t gsb = (uint32_t)__cvta_generic_to_shared(gs);

    auto issue = [&](int chv, int st) {
        uint32_t base = gsb + (uint32_t)st * 8704;
#pragma unroll
        for (int j = 0; j < 2; j++) {
            int i = tid + j * 256;
            int k = i >> 5, c4 = (i & 31) * 4;
            cpa16(base + (uint32_t)(k * 136 + c4) * 4,
                  gB + (size_t)k * HW + (nh * 8 + chv) * 128 + c4);
        }
        cp_commit();
    };

    issue(0, 0); issue(1, 1); issue(2, 2);

    // f chunk (rna) then hoist fragments (CTA-constant across chunks)
    if (tid < 128) {
        float4 v4 = *(const float4*)(g_ft + ((size_t)b * MP + mc * 32) * 16 + tid * 4);
        int m = (tid * 4) >> 4, k = (tid * 4) & 15;
        *(float4*)(fs + m * 20 + k) =
            make_float4(tf32r(v4.x), tf32r(v4.y), tf32r(v4.z), tf32r(v4.w));
    }
    __syncthreads();

    uint32_t fA[2][4];
    {
        const int m0 = mhalf * 16;
#pragma unroll
        for (int ks = 0; ks < 2; ks++) {
            fA[ks][0] = fsu[(m0 + q)     * 20 + ks * 8 + tig];
            fA[ks][1] = fsu[(m0 + q + 8) * 20 + ks * 8 + tig];
            fA[ks][2] = fsu[(m0 + q)     * 20 + ks * 8 + tig + 4];
            fA[ks][3] = fsu[(m0 + q + 8) * 20 + ks * 8 + tig + 4];
        }
    }

    float sm0 = 0.f, sm1 = 0.f;
    const int sm_ = tid >> 3, sc_ = tid & 7;   // coalesced bes store mapping

    for (int ch = 0; ch < 8; ch++) {
        if (ch <= 5)      cp_wait<2>();
        else if (ch == 6) cp_wait<1>();
        else              cp_wait<0>();
        __syncthreads();

        if (ch > 0) {
            const unsigned* bp = bes + ((ch - 1) & 1) * 2176;
            uint4 v0 = *(const uint4*)(bp + sm_ * 68 + sc_ * 8);
            uint4 v1 = *(const uint4*)(bp + sm_ * 68 + sc_ * 8 + 4);
            uint4* dst = (uint4*)(g_be + ((size_t)b * MP + mc * 32 + sm_) * HW
                                  + (nh * 8 + ch - 1) * 128 + sc_ * 16);
            dst[0] = v0; dst[1] = v1;
        }
        if (ch + 3 < 8) issue(ch + 3, (ch + 3) & 3);

        // s tile from stage ch&3
        const uint32_t* gsu = (const uint32_t*)(gs + (ch & 3) * 2176);
        float sc[4][4];
#pragma unroll
        for (int t = 0; t < 4; t++)
#pragma unroll
            for (int j = 0; j < 4; j++) sc[t][j] = 0.f;
#pragma unroll
        for (int ks = 0; ks < 2; ks++)
#pragma unroll
            for (int t = 0; t < 4; t++) {
                uint32_t b0 = gsu[(ks * 8 + tig)     * 136 + ng * 32 + t * 8 + q];
                uint32_t b1 = gsu[(ks * 8 + tig + 4) * 136 + ng * 32 + t * 8 + q];
                mma_tf32(sc[t], fA[ks][0], fA[ks][1], fA[ks][2], fA[ks][3], b0, b1);
            }

        unsigned* bcur = bes + (ch & 1) * 2176;
#pragma unroll
        for (int t = 0; t < 4; t++) {
            float e0 = __expf(sc[t][0]), e1 = __expf(sc[t][1]);
            float e2 = __expf(sc[t][2]), e3 = __expf(sc[t][3]);
            sm0 += e0 + e1;
            sm1 += e2 + e3;
            __nv_bfloat162 p0 = __floats2bfloat162_rn(e0, e1);
            __nv_bfloat162 p1 = __floats2bfloat162_rn(e2, e3);
            int ci = ng * 16 + t * 4 + tig;
            bcur[lr0 * 68 + ci]       = *(unsigned*)&p0;
            bcur[(lr0 + 8) * 68 + ci] = *(unsigned*)&p1;
        }
    }
    __syncthreads();

    // final bes store (chunk 7, buffer parity 1)
    {
        const unsigned* bp = bes + 2176;
        uint4 v0 = *(const uint4*)(bp + sm_ * 68 + sc_ * 8);
        uint4 v1 = *(const uint4*)(bp + sm_ * 68 + sc_ * 8 + 4);
        uint4* dst = (uint4*)(g_be + ((size_t)b * MP + mc * 32 + sm_) * HW
                              + (nh * 8 + 7) * 128 + sc_ * 16);
        dst[0] = v0; dst[1] = v1;
    }

    // partial Z reduce: quad (tig) then across ng warps
    sm0 += __shfl_xor_sync(0xffffffffu, sm0, 1);
    sm0 += __shfl_xor_sync(0xffffffffu, sm0, 2);
    sm1 += __shfl_xor_sync(0xffffffffu, sm1, 1);
    sm1 += __shfl_xor_sync(0xffffffffu, sm1, 2);
    if (tig == 0) {
        sws[lr0][ng]     = sm0;
        sws[lr0 + 8][ng] = sm1;
    }
    __syncthreads();
    if (tid < 32) {
        float Zp = sws[tid][0] + sws[tid][1] + sws[tid][2] + sws[tid][3];
        g_zp[b * 4096 + nh * 1024 + mc * 32 + tid] = Zp;
    }
}

// =====================================================================
// Kernel 2b: finalize — Z = sum of 4 partials, v' = bf16(v * 1/Z).
// Grid: (8 m-eighths, 16 batches), 256 threads.
// =====================================================================
__global__ void __launch_bounds__(256) finalize_kernel()
{
    __shared__ float izs[128];
    const int b  = blockIdx.y;
    const int me = blockIdx.x;        // m range [me*128, me*128+128)
    const int tid = threadIdx.x;

    if (tid < 128) {
        int m = me * 128 + tid;
        const float* zp = g_zp + b * 4096 + m;
        izs[tid] = 1.0f / (zp[0] + zp[1024] + zp[2048] + zp[3072]);
    }
    __syncthreads();

    // v' for all 64 k2 rows, 128 m cols
    for (int i = tid; i < 4096; i += 256) {
        int k2 = i >> 6, m0 = (i & 63) * 2;
        const float* vp = g_v + ((size_t)b * K2 + k2) * MP + me * 128 + m0;
        float2 vv = *(const float2*)vp;
        __nv_bfloat162 p = __floats2bfloat162_rn(vv.x * izs[m0], vv.y * izs[m0 + 1]);
        *(unsigned*)(g_vb + ((size_t)b * K2 + k2) * MP + me * 128 + m0) = *(unsigned*)&p;
    }
}

// =====================================================================
// Kernel 3: o = v' @ expE (bf16 mma + ldmatrix), 4-stage cp.async
// pipeline (one barrier per chunk), then out = gamma*(Wo@o+bo)+x.
// Grid: (32 n-blocks of 128, 16 batches), 256 threads, 8 warps 2x4.
// Stage = v' 5120B + expE 8704B = 13824B; 4 stages = 55296B.
// Epilogue reuses smem as Os[64][132]+WoT[64][128] (66560B request).
// =====================================================================
__global__ void __launch_bounds__(256) attn_out_kernel(
    const float* __restrict__ x, const float* __restrict__ Wo,
    const float* __restrict__ bo, const float* __restrict__ gammap,
    float* __restrict__ out)
{
    extern __shared__ float sm3[];
    const uint32_t sb = (uint32_t)__cvta_generic_to_shared(sm3);

    const int b   = blockIdx.y;
    const int nb  = blockIdx.x;
    const int tid = threadIdx.x;
    const int w   = tid >> 5, lane = tid & 31;
    const int q   = lane >> 2, tig = lane & 3;
    const int rw  = w >> 2, cw = w & 3;

    const uint16_t* beB = g_be + (size_t)b * MP * HW + nb * 128;
    const uint16_t* vbB = g_vb + (size_t)b * K2 * MP;

    const int lrow  = (lane & 7) + ((lane >> 3) & 1) * 8;
    const int lcol8 = (lane >> 4) * 8;

    auto issue = [&](int ch, int st) {
        uint32_t base = sb + (uint32_t)st * 13824;
        {
            int k2 = tid >> 2, mo = (tid & 3) * 8;
            cpa16(base + (uint32_t)(k2 * 80 + (tid & 3) * 16),
                  vbB + (size_t)k2 * MP + ch * 32 + mo);
        }
#pragma unroll
        for (int j = 0; j < 2; j++) {
            int i = tid + j * 256;
            int m = i >> 4, c16 = (i & 15) * 8;
            cpa16(base + 5120 + (uint32_t)(m * 272 + c16 * 2),
                  beB + (size_t)(ch * 32 + m) * HW + c16);
        }
        cp_commit();
    };

    issue(0, 0); issue(1, 1); issue(2, 2);

    float acc[2][4][4];
#pragma unroll
    for (int mt = 0; mt < 2; mt++)
#pragma unroll
        for (int t = 0; t < 4; t++)
#pragma unroll
            for (int j = 0; j < 4; j++) acc[mt][t][j] = 0.f;

    for (int ch = 0; ch < 32; ch++) {
        if (ch <= 29)      cp_wait<2>();
        else if (ch == 30) cp_wait<1>();
        else               cp_wait<0>();
        __syncthreads();

        if (ch + 3 < 32) issue(ch + 3, (ch + 3) & 3);

        const uint32_t vbase = sb + (uint32_t)(ch & 3) * 13824;
        const uint32_t ebase = vbase + 5120;

#pragma unroll
        for (int ks = 0; ks < 2; ks++) {
            uint32_t A[2][4];
#pragma unroll
            for (int mt = 0; mt < 2; mt++)
                ldm4(A[mt], vbase + (uint32_t)((rw * 32 + mt * 16 + lrow) * 80
                                               + (ks * 16 + lcol8) * 2));
#pragma unroll
            for (int nh = 0; nh < 2; nh++) {
                uint32_t B4[4];
                ldm4t(B4, ebase + (uint32_t)((ks * 16 + lrow) * 272
                                             + (cw * 32 + nh * 16 + lcol8) * 2));
                mma_bf16(acc[0][nh * 2],     A[0][0], A[0][1], A[0][2], A[0][3], B4[0], B4[1]);
                mma_bf16(acc[1][nh * 2],     A[1][0], A[1][1], A[1][2], A[1][3], B4[0], B4[1]);
                mma_bf16(acc[0][nh * 2 + 1], A[0][0], A[0][1], A[0][2], A[0][3], B4[2], B4[3]);
                mma_bf16(acc[1][nh * 2 + 1], A[1][0], A[1][1], A[1][2], A[1][3], B4[2], B4[3]);
            }
        }
    }
    __syncthreads();

    // ---------------- epilogue: out = gamma*(Wo @ o + bo) + x ----------------
    float* Os  = sm3;          // [64][132]
    float* WoT = sm3 + 8448;   // [64][128]

#pragma unroll
    for (int mt = 0; mt < 2; mt++)
#pragma unroll
        for (int t = 0; t < 4; t++) {
            int rr = rw * 32 + mt * 16 + q;
            int cc = cw * 32 + t * 8 + 2 * tig;
            *(float2*)(Os + rr * 132 + cc)       = make_float2(acc[mt][t][0], acc[mt][t][1]);
            *(float2*)(Os + (rr + 8) * 132 + cc) = make_float2(acc[mt][t][2], acc[mt][t][3]);
        }
    for (int i = tid; i < 8192; i += 256) {
        int k = i >> 7, cc = i & 127;
        WoT[i] = Wo[cc * 64 + k];
    }
    __syncthreads();

    const int tx = tid & 15, ty = tid >> 4;
    const float gma = *gammap;
    float acc2[8][8];
#pragma unroll
    for (int i = 0; i < 8; i++)
#pragma unroll
        for (int j = 0; j < 8; j++) acc2[i][j] = 0.f;

#pragma unroll 4
    for (int k = 0; k < 64; k++) {
        float4 w0 = *(const float4*)(WoT + k * 128 + ty * 8);
        float4 w1 = *(const float4*)(WoT + k * 128 + ty * 8 + 4);
        float4 o0 = *(const float4*)(Os + k * 132 + tx * 8);
        float4 o1 = *(const float4*)(Os + k * 132 + tx * 8 + 4);
        float wv[8] = {w0.x, w0.y, w0.z, w0.w, w1.x, w1.y, w1.z, w1.w};
        float ov[8] = {o0.x, o0.y, o0.z, o0.w, o1.x, o1.y, o1.z, o1.w};
#pragma unroll
        for (int i = 0; i < 8; i++)
#pragma unroll
            for (int j = 0; j < 8; j++)
                acc2[i][j] = fmaf(wv[i], ov[j], acc2[i][j]);
    }

#pragma unroll
    for (int rr = 0; rr < 8; rr++) {
        const int cc = ty * 8 + rr;
        const float bias = bo[cc];
        const size_t off = (size_t)(b * NC + cc) * HW + nb * 128 + tx * 8;
        float4 x0 = *(const float4*)(x + off);
        float4 x1 = *(const float4*)(x + off + 4);
        float4 rA, rB;
        rA.x = fmaf(gma, acc2[rr][0] + bias, x0.x);
        rA.y = fmaf(gma, acc2[rr][1] + bias, x0.y);
        rA.z = fmaf(gma, acc2[rr][2] + bias, x0.z);
        rA.w = fmaf(gma, acc2[rr][3] + bias, x0.w);
        rB.x = fmaf(gma, acc2[rr][4] + bias, x1.x);
        rB.y = fmaf(gma, acc2[rr][5] + bias, x1.y);
        rB.z = fmaf(gma, acc2[rr][6] + bias, x1.z);
        rB.w = fmaf(gma, acc2[rr][7] + bias, x1.w);
        *(float4*)(out + off)     = rA;
        *(float4*)(out + off + 4) = rB;
    }
}

// =====================================================================
extern "C" void kernel_launch(void* const* d_in, const int* in_sizes, int n_in,
                              void* d_out, int out_size)
{
    (void)in_sizes; (void)n_in; (void)out_size;
    const float* x     = (const float*)d_in[0];
    const float* Wf    = (const float*)d_in[1];
    const float* bf    = (const float*)d_in[2];
    const float* Wg    = (const float*)d_in[3];
    const float* bg    = (const float*)d_in[4];
    const float* Wh    = (const float*)d_in[5];
    const float* bh    = (const float*)d_in[6];
    const float* Wo    = (const float*)d_in[7];
    const float* bo    = (const float*)d_in[8];
    const float* gamma = (const float*)d_in[9];
    float* out = (float*)d_out;

    cudaFuncSetAttribute(conv_pool_kernel,
                         cudaFuncAttributeMaxDynamicSharedMemorySize, 120320);
    cudaFuncSetAttribute(stats_exp_kernel,
                         cudaFuncAttributeMaxDynamicSharedMemorySize, 54784);
    cudaFuncSetAttribute(attn_out_kernel,
                         cudaFuncAttributeMaxDynamicSharedMemorySize, 66560);

    conv_pool_kernel<<<dim3(32, NB), 256, 120320>>>(x, Wf, bf, Wg, bg, Wh, bh);
    stats_exp_kernel<<<dim3(32, 4, NB), 256, 54784>>>();
    finalize_kernel<<<dim3(8, NB), 256>>>();
    attn_out_kernel<<<dim3(32, NB), 256, 66560>>>(x, Wo, bo, gamma, out);
}